// round 3
// baseline (speedup 1.0000x reference)
#include <cuda_runtime.h>

#define N 1024
#define H 96
#define E 16384

// ---------------- scratch (device globals; no allocation allowed) ----------
__device__ float g_bufA[N*H];
__device__ float g_bufB[N*H];
__device__ float g_m[N*H];
__device__ float g_s[N*H];
__device__ int   g_icnt[N];
__device__ float g_hi[N*H];
__device__ float g_hjbT[H*N];          // transposed: [k][n]
__device__ int   g_src[E];
__device__ int   g_tgt[E];
__device__ unsigned short g_list[N*N]; // compacted active-j per row
__device__ int   g_rcnt[N];
__device__ float g_WihT[96*288];
__device__ float g_WhhT[96*288];
__device__ float g_WaiT[96*96];
__device__ float g_WajT[96*96];
__device__ float g_Wo1T[96*96];
__device__ float g_Wo2T[96*96];

__device__ __forceinline__ float sigf(float v){
    // 1/(1+2^(-v*log2e)) via approx ex2 + approx rcp (2 MUFU ops)
    float e;
    asm("ex2.approx.f32 %0, %1;" : "=f"(e) : "f"(v * -1.4426950408889634f));
    float r;
    asm("rcp.approx.f32 %0, %1;" : "=f"(r) : "f"(1.0f + e));
    return r;
}
__device__ __forceinline__ float tanhfast(float v){
    return fmaf(2.0f, sigf(2.0f*v), -1.0f);
}
__device__ __forceinline__ float leaky(float v){
    return (v >= 0.0f) ? v : 0.01f * v;
}

// ---------------- zero the edge-count histogram -----------------------------
__global__ void k_zero(){
    g_icnt[threadIdx.x] = 0;
}

// ---------------- decode edge_index (int64 vs int32 storage) + histogram ----
__global__ void k_decode(const int* __restrict__ ei32){
    int e = blockIdx.x * blockDim.x + threadIdx.x;
    if (e >= E) return;
    int odd_or = 0;
    #pragma unroll
    for (int q = 0; q < 16; q++) odd_or |= ei32[2*q + 1];
    int s, t;
    if (odd_or == 0){            // int64 layout
        s = ei32[2*e];
        t = ei32[2*(E + e)];
    } else {                     // int32 layout
        s = ei32[e];
        t = ei32[E + e];
    }
    if ((unsigned)s >= N) s = -1;
    if ((unsigned)t >= N) t = -1;
    g_src[e] = s;
    g_tgt[e] = t;
    if (t >= 0) atomicAdd(&g_icnt[t], 1);
}

// ---------------- compact adjacency rows (warp per row, ballot scan) --------
__global__ void k_rows(const int* __restrict__ adj){
    int warp = threadIdx.x >> 5, lane = threadIdx.x & 31;
    int row = blockIdx.x * 8 + warp;
    const int* arow = adj + row * N;
    int base = 0;
    for (int w = 0; w < 32; w++){
        int j = w*32 + lane;
        int a = arow[j];
        unsigned m = __ballot_sync(0xffffffffu, a == 1);
        if (a == 1){
            int pos = base + __popc(m & ((1u << lane) - 1u));
            g_list[row*N + pos] = (unsigned short)j;
        }
        base += __popc(m);
    }
    if (lane == 0) g_rcnt[row] = base;
}

// ---------------- prep: transpose weights for coalesced dot reads -----------
__global__ void k_prep(const float* __restrict__ Wih, const float* __restrict__ Whh,
                       const float* __restrict__ Wa1,
                       const float* __restrict__ Wo1, const float* __restrict__ Wo2){
    int t = blockIdx.x * blockDim.x + threadIdx.x;
    if (t < 288*96){
        int c = t / 96, k = t % 96;
        g_WihT[k*288 + c] = Wih[t];
        g_WhhT[k*288 + c] = Whh[t];
    }
    if (t < 96*192){
        int h = t / 192, k2 = t % 192;
        float v = Wa1[t];
        if (k2 < 96) g_WaiT[k2*96 + h] = v;
        else         g_WajT[(k2-96)*96 + h] = v;
    }
    if (t < 96*96){
        int h = t / 96, k = t % 96;
        g_Wo1T[k*96 + h] = Wo1[t];
        g_Wo2T[k*96 + h] = Wo2[t];
    }
}

// ---------------- init: x = leaky(x[:, :9] @ W_init.T + b_init) ------------
__global__ void k_init(const float* __restrict__ xin, const float* __restrict__ Wi,
                       const float* __restrict__ bi){
    // 4 nodes per block, 384 threads
    int r = threadIdx.x / 96, h = threadIdx.x % 96;
    int n = blockIdx.x * 4 + r;
    __shared__ float xr[4][10];
    if (threadIdx.x < 40){
        int rr = threadIdx.x / 10, c = threadIdx.x % 10;
        xr[rr][c] = xin[(blockIdx.x*4 + rr)*10 + c];
    }
    __syncthreads();
    float a = bi[h];
    #pragma unroll
    for (int k = 0; k < 9; k++) a = fmaf(xr[r][k], Wi[h*9 + k], a);
    g_bufA[n*H + h] = leaky(a);
}

// ---------------- m = x @ W_ggc ; zero s -----------------------------------
__global__ void k_mm(int src, const float* __restrict__ Wg){
    const float* x = src ? g_bufB : g_bufA;
    int tid = threadIdx.x;
    int r = tid / 96, h = tid % 96;
    int base = blockIdx.x * 384;          // 4 nodes * 96
    __shared__ float xr[4][96];
    xr[r][h] = x[base + tid];             // contiguous
    __syncthreads();
    float a0 = 0.f, a1 = 0.f;
    #pragma unroll 8
    for (int k = 0; k < 96; k += 2){
        a0 = fmaf(xr[r][k],   Wg[k*96 + h],     a0);
        a1 = fmaf(xr[r][k+1], Wg[(k+1)*96 + h], a1);
    }
    g_m[base + tid] = a0 + a1;
    g_s[base + tid] = 0.f;
}

// ---------------- segment sum over edges (validated indices) ----------------
__global__ void k_scatter(){
    int el = threadIdx.x / 96, h = threadIdx.x % 96;
    int e0 = blockIdx.x * 128;
    #pragma unroll 4
    for (int it = 0; it < 32; it++){
        int e = e0 + it*4 + el;
        int s = g_src[e];
        int t = g_tgt[e];
        if (s >= 0 && t >= 0)
            atomicAdd(&g_s[t*H + h], g_m[s*H + h]);
    }
}

// ---------------- GRU update + attention features (hi, hjbT) ----------------
__global__ void k_gru(int src,
                      const float* __restrict__ bih, const float* __restrict__ bhh,
                      const float* __restrict__ ba1){
    float* x = src ? g_bufB : g_bufA;
    int tid = threadIdx.x;
    int r = tid / 96, h = tid % 96;
    int n = blockIdx.x * 2 + r;
    int base = blockIdx.x * 192;
    __shared__ float ag[2][96], xr[2][96], xn[2][96];
    {
        float c = (float)g_icnt[n];
        float inv;
        asm("rcp.approx.f32 %0, %1;" : "=f"(inv) : "f"(fmaxf(c, 1.0f)));
        ag[r][h] = g_s[base + tid] * inv;
        xr[r][h] = x[base + tid];
    }
    __syncthreads();
    float gir = bih[h], giz = bih[h+96], gin = bih[h+192];
    float ghr = bhh[h], ghz = bhh[h+96], ghn = bhh[h+192];
    #pragma unroll 4
    for (int k = 0; k < 96; k++){
        float a = ag[r][k], xv = xr[r][k];
        gir = fmaf(a,  g_WihT[k*288 + h],       gir);
        giz = fmaf(a,  g_WihT[k*288 + h + 96],  giz);
        gin = fmaf(a,  g_WihT[k*288 + h + 192], gin);
        ghr = fmaf(xv, g_WhhT[k*288 + h],       ghr);
        ghz = fmaf(xv, g_WhhT[k*288 + h + 96],  ghz);
        ghn = fmaf(xv, g_WhhT[k*288 + h + 192], ghn);
    }
    float rr = sigf(gir + ghr);
    float zz = sigf(giz + ghz);
    float nn = tanhfast(gin + rr * ghn);
    float xv = (1.0f - zz) * nn + zz * xr[r][h];
    xn[r][h] = xv;
    x[base + tid] = xv;
    __syncthreads();
    float hiv = 0.f, hjv = ba1[h];
    #pragma unroll 4
    for (int k = 0; k < 96; k++){
        float xk = xn[r][k];
        hiv = fmaf(xk, g_WaiT[k*96 + h], hiv);
        hjv = fmaf(xk, g_WajT[k*96 + h], hjv);
    }
    g_hi[n*96 + h]    = hiv;
    g_hjbT[h*N + n]   = hjv;   // transposed store
}

// ---------------- fused attention coeff + sparse row matvec -----------------
// For row i: c[idx] = sig( sum_k sig(hi[i,k] + hjbT[k, j]) * Wa2[k] + ba2 )
//            x_out[i,:] = sum_idx c[idx] * x[list[idx], :]
__global__ __launch_bounds__(256) void k_att(int src,
                      const float* __restrict__ Wa2, const float* __restrict__ ba2){
    const float* x = src ? g_bufB : g_bufA;
    float* xout    = src ? g_bufA : g_bufB;
    int i = blockIdx.x;
    int tid = threadIdx.x;
    __shared__ float hi_s[96], w_s[96], c_sh[1024];
    __shared__ unsigned short list_sh[1024];
    if (tid < 96){
        hi_s[tid] = g_hi[i*96 + tid];
        w_s[tid]  = Wa2[tid];
    }
    __syncthreads();
    int cnt = g_rcnt[i];
    float bb = ba2[0];
    for (int idx = tid; idx < cnt; idx += 256){
        int j = g_list[i*N + idx];
        list_sh[idx] = (unsigned short)j;
        const float* hjT = g_hjbT + j;
        float s0 = 0.f, s1 = 0.f, s2 = 0.f, s3 = 0.f;
        #pragma unroll
        for (int k = 0; k < 96; k += 4){
            s0 = fmaf(sigf(hi_s[k]   + hjT[(k)*N]),   w_s[k],   s0);
            s1 = fmaf(sigf(hi_s[k+1] + hjT[(k+1)*N]), w_s[k+1], s1);
            s2 = fmaf(sigf(hi_s[k+2] + hjT[(k+2)*N]), w_s[k+2], s2);
            s3 = fmaf(sigf(hi_s[k+3] + hjT[(k+3)*N]), w_s[k+3], s3);
        }
        c_sh[idx] = sigf(((s0 + s1) + (s2 + s3)) + bb);
    }
    __syncthreads();
    if (tid < 96){
        float a0 = 0.f, a1 = 0.f, a2 = 0.f, a3 = 0.f;
        int idx = 0;
        for (; idx + 4 <= cnt; idx += 4){
            a0 = fmaf(c_sh[idx],   x[list_sh[idx]*96   + tid], a0);
            a1 = fmaf(c_sh[idx+1], x[list_sh[idx+1]*96 + tid], a1);
            a2 = fmaf(c_sh[idx+2], x[list_sh[idx+2]*96 + tid], a2);
            a3 = fmaf(c_sh[idx+3], x[list_sh[idx+3]*96 + tid], a3);
        }
        for (; idx < cnt; idx++)
            a0 = fmaf(c_sh[idx], x[list_sh[idx]*96 + tid], a0);
        xout[i*96 + tid] = (a0 + a1) + (a2 + a3);
    }
}

// ---------------- output head ----------------------------------------------
__global__ void k_out(const float* __restrict__ bo1, const float* __restrict__ bo2,
                      const float* __restrict__ Wp1, const float* __restrict__ bp1,
                      const float* __restrict__ Wp2, const float* __restrict__ bp2,
                      float* __restrict__ out){
    const float* x = g_bufA;   // after 2 unrolls data sits in bufA
    int n = blockIdx.x, h = threadIdx.x;
    int w = h >> 5, lane = h & 31;
    __shared__ float x0[96], x1[96], sw1[3], sw2[3];
    x0[h] = x[n*96 + h];
    __syncthreads();
    float a = bo1[h];
    #pragma unroll 4
    for (int k = 0; k < 96; k++) a = fmaf(x0[k], g_Wo1T[k*96 + h], a);
    x1[h] = leaky(a);
    __syncthreads();
    float b = bo2[h];
    #pragma unroll 4
    for (int k = 0; k < 96; k++) b = fmaf(x1[k], g_Wo2T[k*96 + h], b);
    float v = leaky(b);
    float r1 = v * Wp1[h];
    float r2 = v * Wp2[h];
    #pragma unroll
    for (int o = 16; o; o >>= 1){
        r1 += __shfl_xor_sync(0xffffffffu, r1, o);
        r2 += __shfl_xor_sync(0xffffffffu, r2, o);
    }
    if (lane == 0){ sw1[w] = r1; sw2[w] = r2; }
    __syncthreads();
    if (h == 0){
        out[n]     = sigf(sw1[0] + sw1[1] + sw1[2] + bp1[0]);
        out[N + n] = sigf(sw2[0] + sw2[1] + sw2[2] + bp2[0]);
    }
}

// ---------------- launch ----------------------------------------------------
extern "C" void kernel_launch(void* const* d_in, const int* in_sizes, int n_in,
                              void* d_out, int out_size){
    const float* x_in  = (const float*)d_in[0];
    const int*   ei32  = (const int*)d_in[1];
    const int*   adj   = (const int*)d_in[2];
    const float* W_init= (const float*)d_in[3];
    const float* b_init= (const float*)d_in[4];
    const float* W_ggc = (const float*)d_in[5];
    const float* W_ih  = (const float*)d_in[6];
    const float* W_hh  = (const float*)d_in[7];
    const float* b_ih  = (const float*)d_in[8];
    const float* b_hh  = (const float*)d_in[9];
    const float* Wa1   = (const float*)d_in[10];
    const float* ba1   = (const float*)d_in[11];
    const float* Wa2   = (const float*)d_in[12];
    const float* ba2   = (const float*)d_in[13];
    const float* Wo1   = (const float*)d_in[14];
    const float* bo1   = (const float*)d_in[15];
    const float* Wo2   = (const float*)d_in[16];
    const float* bo2   = (const float*)d_in[17];
    const float* Wp1   = (const float*)d_in[18];
    const float* bp1   = (const float*)d_in[19];
    const float* Wp2   = (const float*)d_in[20];
    const float* bp2   = (const float*)d_in[21];
    float* out = (float*)d_out;

    k_zero<<<1, N>>>();
    k_decode<<<E/256, 256>>>(ei32);
    k_prep<<<(288*96 + 255)/256, 256>>>(W_ih, W_hh, Wa1, Wo1, Wo2);
    k_rows<<<N/8, 256>>>(adj);
    k_init<<<N/4, 384>>>(x_in, W_init, b_init);
    for (int u = 0; u < 2; u++){
        k_mm<<<N/4, 384>>>(u, W_ggc);
        k_scatter<<<E/128, 384>>>();
        k_gru<<<N/2, 192>>>(u, b_ih, b_hh, ba1);
        k_att<<<N, 256>>>(u, Wa2, ba2);
    }
    k_out<<<N, 96>>>(bo1, bo2, Wp1, bp1, Wp2, bp2, out);
}

// round 4
// speedup vs baseline: 1.5690x; 1.5690x over previous
#include <cuda_runtime.h>

#define N 1024
#define H 96
#define E 16384
#define LOG2E 1.4426950408889634f

// ---------------- scratch (device globals; no allocation allowed) ----------
__device__ float g_bufA[N*H];
__device__ float g_bufB[N*H];
__device__ float g_m[N*H];
__device__ float g_s[N*H];
__device__ int   g_icnt[N];
__device__ float g_hi[N*H];            // pre-scaled by -log2e
__device__ float g_hjb[N*H];           // pre-scaled by -log2e, includes ba1
__device__ int   g_src[E];
__device__ int   g_tgt[E];
__device__ unsigned short g_list[N*N]; // compacted active-j per row (sorted)
__device__ int   g_rcnt[N];
__device__ int   g_toff[N*9];          // per-row tile offsets (8 tiles of 128 + end)
__device__ float g_WihT[96*288];
__device__ float g_WhhT[96*288];
__device__ float g_WaiT[96*96];
__device__ float g_WajT[96*96];
__device__ float g_Wo1T[96*96];
__device__ float g_Wo2T[96*96];

__device__ __forceinline__ float sigf(float v){
    float e;
    asm("ex2.approx.f32 %0, %1;" : "=f"(e) : "f"(v * -LOG2E));
    float r;
    asm("rcp.approx.f32 %0, %1;" : "=f"(r) : "f"(1.0f + e));
    return r;
}
// input already scaled by -log2e
__device__ __forceinline__ float sigf_pre(float v){
    float e;
    asm("ex2.approx.f32 %0, %1;" : "=f"(e) : "f"(v));
    float r;
    asm("rcp.approx.f32 %0, %1;" : "=f"(r) : "f"(1.0f + e));
    return r;
}
__device__ __forceinline__ float tanhfast(float v){
    return fmaf(2.0f, sigf(2.0f*v), -1.0f);
}
__device__ __forceinline__ float leaky(float v){
    return (v >= 0.0f) ? v : 0.01f * v;
}

// ---------------- zero edge-count histogram ---------------------------------
__global__ void k_zero(){ g_icnt[threadIdx.x] = 0; }

// ---------------- decode edge_index (int64 vs int32 storage) + histogram ----
__global__ void k_decode(const int* __restrict__ ei32){
    int e = blockIdx.x * blockDim.x + threadIdx.x;
    if (e >= E) return;
    int odd_or = 0;
    #pragma unroll
    for (int q = 0; q < 16; q++) odd_or |= ei32[2*q + 1];
    int s, t;
    if (odd_or == 0){ s = ei32[2*e];  t = ei32[2*(E + e)]; }   // int64 layout
    else            { s = ei32[e];    t = ei32[E + e];      }  // int32 layout
    if ((unsigned)s >= N) s = -1;
    if ((unsigned)t >= N) t = -1;
    g_src[e] = s;
    g_tgt[e] = t;
    if (t >= 0) atomicAdd(&g_icnt[t], 1);
}

// ---------------- compact adjacency rows + tile offsets ---------------------
__global__ void k_rows(const int* __restrict__ adj){
    int warp = threadIdx.x >> 5, lane = threadIdx.x & 31;
    int row = blockIdx.x * 8 + warp;
    const int* arow = adj + row * N;
    int base = 0;
    for (int w = 0; w < 32; w++){
        if ((w & 3) == 0 && lane == 0) g_toff[row*9 + (w >> 2)] = base;
        int j = w*32 + lane;
        int a = arow[j];
        unsigned m = __ballot_sync(0xffffffffu, a == 1);
        if (a == 1){
            int pos = base + __popc(m & ((1u << lane) - 1u));
            g_list[row*N + pos] = (unsigned short)j;
        }
        base += __popc(m);
    }
    if (lane == 0){ g_rcnt[row] = base; g_toff[row*9 + 8] = base; }
}

// ---------------- prep: weight transposes -----------------------------------
__global__ void k_prep(const float* __restrict__ Wih, const float* __restrict__ Whh,
                       const float* __restrict__ Wa1,
                       const float* __restrict__ Wo1, const float* __restrict__ Wo2){
    int t = blockIdx.x * blockDim.x + threadIdx.x;
    if (t < 288*96){
        int c = t / 96, k = t % 96;
        g_WihT[k*288 + c] = Wih[t];
        g_WhhT[k*288 + c] = Whh[t];
    }
    if (t < 96*192){
        int h = t / 192, k2 = t % 192;
        float v = Wa1[t];
        if (k2 < 96) g_WaiT[k2*96 + h] = v;
        else         g_WajT[(k2-96)*96 + h] = v;
    }
    if (t < 96*96){
        int h = t / 96, k = t % 96;
        g_Wo1T[k*96 + h] = Wo1[t];
        g_Wo2T[k*96 + h] = Wo2[t];
    }
}

// ---------------- init: x = leaky(x[:, :9] @ W_init.T + b_init) -------------
__global__ void k_init(const float* __restrict__ xin, const float* __restrict__ Wi,
                       const float* __restrict__ bi){
    int r = threadIdx.x / 96, h = threadIdx.x % 96;
    int n = blockIdx.x * 4 + r;
    __shared__ float xr[4][10];
    if (threadIdx.x < 40){
        int rr = threadIdx.x / 10, c = threadIdx.x % 10;
        xr[rr][c] = xin[(blockIdx.x*4 + rr)*10 + c];
    }
    __syncthreads();
    float a = bi[h];
    #pragma unroll
    for (int k = 0; k < 9; k++) a = fmaf(xr[r][k], Wi[h*9 + k], a);
    g_bufA[n*H + h] = leaky(a);
}

// ---------------- m = x @ W_ggc ; zero s ------------------------------------
__global__ void k_mm(int src, const float* __restrict__ Wg){
    const float* x = src ? g_bufB : g_bufA;
    int tid = threadIdx.x;
    int r = tid / 96, h = tid % 96;
    int base = blockIdx.x * 384;
    __shared__ float xr[4][96];
    xr[r][h] = x[base + tid];
    __syncthreads();
    float a0 = 0.f, a1 = 0.f;
    #pragma unroll 8
    for (int k = 0; k < 96; k += 2){
        a0 = fmaf(xr[r][k],   Wg[k*96 + h],     a0);
        a1 = fmaf(xr[r][k+1], Wg[(k+1)*96 + h], a1);
    }
    g_m[base + tid] = a0 + a1;
    g_s[base + tid] = 0.f;
}

// ---------------- segment sum over edges (thread per (edge,h)) --------------
__global__ void k_scatter(){
    int g = blockIdx.x * 256 + threadIdx.x;   // g < E*96
    int e = g / 96, h = g - e*96;
    int s = g_src[e];
    int t = g_tgt[e];
    if (s >= 0 && t >= 0)
        atomicAdd(&g_s[t*96 + h], g_m[s*96 + h]);
}

// ---------------- GRU update + scaled attention features --------------------
__global__ __launch_bounds__(384) void k_gru(int src,
                      const float* __restrict__ bih, const float* __restrict__ bhh,
                      const float* __restrict__ ba1){
    float* x = src ? g_bufB : g_bufA;
    int tid = threadIdx.x;
    int r = tid / 96, h = tid - r*96;
    int n = blockIdx.x * 4 + r;
    int base = blockIdx.x * 384;
    __shared__ float ag[4][96], xr[4][96], xn[4][96];
    {
        float c = (float)g_icnt[n];
        float inv;
        asm("rcp.approx.f32 %0, %1;" : "=f"(inv) : "f"(fmaxf(c, 1.0f)));
        ag[r][h] = g_s[base + tid] * inv;
        xr[r][h] = x[base + tid];
    }
    __syncthreads();
    float gir = bih[h], giz = bih[h+96], gin = bih[h+192];
    float ghr = bhh[h], ghz = bhh[h+96], ghn = bhh[h+192];
    #pragma unroll 4
    for (int k = 0; k < 96; k++){
        float a = ag[r][k], xv = xr[r][k];
        gir = fmaf(a,  g_WihT[k*288 + h],       gir);
        giz = fmaf(a,  g_WihT[k*288 + h + 96],  giz);
        gin = fmaf(a,  g_WihT[k*288 + h + 192], gin);
        ghr = fmaf(xv, g_WhhT[k*288 + h],       ghr);
        ghz = fmaf(xv, g_WhhT[k*288 + h + 96],  ghz);
        ghn = fmaf(xv, g_WhhT[k*288 + h + 192], ghn);
    }
    float rr = sigf(gir + ghr);
    float zz = sigf(giz + ghz);
    float nn = tanhfast(gin + rr * ghn);
    float xv = (1.0f - zz) * nn + zz * xr[r][h];
    xn[r][h] = xv;
    x[base + tid] = xv;
    __syncthreads();
    float hiv = 0.f, hjv = ba1[h];
    #pragma unroll 4
    for (int k = 0; k < 96; k++){
        float xk = xn[r][k];
        hiv = fmaf(xk, g_WaiT[k*96 + h], hiv);
        hjv = fmaf(xk, g_WajT[k*96 + h], hjv);
    }
    g_hi[n*96 + h]  = -LOG2E * hiv;     // pre-scale for sigf_pre
    g_hjb[n*96 + h] = -LOG2E * hjv;
}

// ---------------- fused attention coeff + sparse row matvec (j-tiled) -------
// smem layout (floats): hj[128*97] | hi[384] | w[96] | c[512] | lj[256(=512 u16)]
#define SM_HJ   0
#define SM_HI   (128*97)
#define SM_W    (SM_HI + 384)
#define SM_C    (SM_W + 96)
#define SM_LJ   (SM_C + 512)
#define SM_FLOATS (SM_LJ + 256)

__global__ __launch_bounds__(384, 2) void k_att(int src,
                      const float* __restrict__ Wa2, const float* __restrict__ ba2){
    extern __shared__ float dsm[];
    float* hj_s = dsm + SM_HJ;
    float* hi_s = dsm + SM_HI;
    float* w_s  = dsm + SM_W;
    float* c_sh = dsm + SM_C;
    unsigned short* lj_sh = (unsigned short*)(dsm + SM_LJ);
    __shared__ int st[4], cr[4];

    const float* x = src ? g_bufB : g_bufA;
    float* xout    = src ? g_bufA : g_bufB;
    int i0 = blockIdx.x * 4;
    int tid = threadIdx.x;
    int rB = tid / 96, hB = tid - rB*96;

    hi_s[tid] = g_hi[i0*96 + tid];             // 4 rows x 96
    if (tid < 96) w_s[tid] = Wa2[tid];
    float bb = ba2[0];
    float accE = 0.f, accO = 0.f;

    for (int t = 0; t < 8; t++){
        __syncthreads();
        // stage hj tile (coalesced; 48KB)
        const float* gsrc = g_hjb + t*(128*96);
        #pragma unroll
        for (int q = 0; q < 32; q++){
            int idx = q*384 + tid;
            int jl = idx / 96, k = idx - jl*96;
            hj_s[jl*97 + k] = gsrc[idx];
        }
        if (tid < 4){
            int i = i0 + tid;
            int a = g_toff[i*9 + t];
            st[tid] = a;
            cr[tid] = g_toff[i*9 + t + 1] - a;
        }
        __syncthreads();
        int c0 = cr[0], c1 = cr[1], c2 = cr[2], c3 = cr[3];
        int p1 = c0, p2 = c0 + c1, p3 = p2 + c2, tot = p3 + c3;
        // phase A: coeff per active pair
        for (int p = tid; p < tot; p += 384){
            int rr = (p >= p1) + (p >= p2) + (p >= p3);
            int seg = (rr == 0) ? 0 : (rr == 1) ? p1 : (rr == 2) ? p2 : p3;
            int local = p - seg;
            int j = g_list[(i0 + rr)*N + st[rr] + local];
            int jl = j - t*128;
            lj_sh[rr*128 + local] = (unsigned short)jl;
            const float* hj = hj_s + jl*97;
            const float* hi = hi_s + rr*96;
            float s0 = 0.f, s1 = 0.f, s2 = 0.f, s3 = 0.f;
            #pragma unroll
            for (int k = 0; k < 96; k += 4){
                s0 = fmaf(sigf_pre(hi[k]   + hj[k]),   w_s[k],   s0);
                s1 = fmaf(sigf_pre(hi[k+1] + hj[k+1]), w_s[k+1], s1);
                s2 = fmaf(sigf_pre(hi[k+2] + hj[k+2]), w_s[k+2], s2);
                s3 = fmaf(sigf_pre(hi[k+3] + hj[k+3]), w_s[k+3], s3);
            }
            c_sh[rr*128 + local] = sigf(((s0 + s1) + (s2 + s3)) + bb);
        }
        __syncthreads();
        // phase B: x_out accumulate (thread = (row, h), coalesced x reads)
        int myc = cr[rB];
        const float* xb = x + t*(128*96) + hB;
        const float* cb = c_sh + rB*128;
        const unsigned short* lb = lj_sh + rB*128;
        int p = 0;
        for (; p + 2 <= myc; p += 2){
            int jl0 = lb[p], jl1 = lb[p+1];
            accE = fmaf(cb[p],   xb[jl0*96], accE);
            accO = fmaf(cb[p+1], xb[jl1*96], accO);
        }
        if (p < myc) accE = fmaf(cb[p], xb[lb[p]*96], accE);
    }
    xout[(i0 + rB)*96 + hB] = accE + accO;
}

// ---------------- output head -----------------------------------------------
__global__ void k_out(const float* __restrict__ bo1, const float* __restrict__ bo2,
                      const float* __restrict__ Wp1, const float* __restrict__ bp1,
                      const float* __restrict__ Wp2, const float* __restrict__ bp2,
                      float* __restrict__ out){
    const float* x = g_bufA;   // after 2 unrolls data sits in bufA
    int n = blockIdx.x, h = threadIdx.x;
    int w = h >> 5, lane = h & 31;
    __shared__ float x0[96], x1[96], sw1[3], sw2[3];
    x0[h] = x[n*96 + h];
    __syncthreads();
    float a = bo1[h];
    #pragma unroll 4
    for (int k = 0; k < 96; k++) a = fmaf(x0[k], g_Wo1T[k*96 + h], a);
    x1[h] = leaky(a);
    __syncthreads();
    float b = bo2[h];
    #pragma unroll 4
    for (int k = 0; k < 96; k++) b = fmaf(x1[k], g_Wo2T[k*96 + h], b);
    float v = leaky(b);
    float r1 = v * Wp1[h];
    float r2 = v * Wp2[h];
    #pragma unroll
    for (int o = 16; o; o >>= 1){
        r1 += __shfl_xor_sync(0xffffffffu, r1, o);
        r2 += __shfl_xor_sync(0xffffffffu, r2, o);
    }
    if (lane == 0){ sw1[w] = r1; sw2[w] = r2; }
    __syncthreads();
    if (h == 0){
        out[n]     = sigf(sw1[0] + sw1[1] + sw1[2] + bp1[0]);
        out[N + n] = sigf(sw2[0] + sw2[1] + sw2[2] + bp2[0]);
    }
}

// ---------------- launch -----------------------------------------------------
extern "C" void kernel_launch(void* const* d_in, const int* in_sizes, int n_in,
                              void* d_out, int out_size){
    const float* x_in  = (const float*)d_in[0];
    const int*   ei32  = (const int*)d_in[1];
    const int*   adj   = (const int*)d_in[2];
    const float* W_init= (const float*)d_in[3];
    const float* b_init= (const float*)d_in[4];
    const float* W_ggc = (const float*)d_in[5];
    const float* W_ih  = (const float*)d_in[6];
    const float* W_hh  = (const float*)d_in[7];
    const float* b_ih  = (const float*)d_in[8];
    const float* b_hh  = (const float*)d_in[9];
    const float* Wa1   = (const float*)d_in[10];
    const float* ba1   = (const float*)d_in[11];
    const float* Wa2   = (const float*)d_in[12];
    const float* ba2   = (const float*)d_in[13];
    const float* Wo1   = (const float*)d_in[14];
    const float* bo1   = (const float*)d_in[15];
    const float* Wo2   = (const float*)d_in[16];
    const float* bo2   = (const float*)d_in[17];
    const float* Wp1   = (const float*)d_in[18];
    const float* bp1   = (const float*)d_in[19];
    const float* Wp2   = (const float*)d_in[20];
    const float* bp2   = (const float*)d_in[21];
    float* out = (float*)d_out;

    static int smem_set = 0;
    (void)smem_set;
    cudaFuncSetAttribute(k_att, cudaFuncAttributeMaxDynamicSharedMemorySize,
                         SM_FLOATS * (int)sizeof(float));

    k_zero<<<1, N>>>();
    k_decode<<<E/256, 256>>>(ei32);
    k_prep<<<(288*96 + 255)/256, 256>>>(W_ih, W_hh, Wa1, Wo1, Wo2);
    k_rows<<<N/8, 256>>>(adj);
    k_init<<<N/4, 384>>>(x_in, W_init, b_init);
    for (int u = 0; u < 2; u++){
        k_mm<<<N/4, 384>>>(u, W_ggc);
        k_scatter<<<(E*96)/256, 256>>>();
        k_gru<<<N/4, 384>>>(u, b_ih, b_hh, ba1);
        k_att<<<N/4, 384, SM_FLOATS * sizeof(float)>>>(u, Wa2, ba2);
    }
    k_out<<<N, 96>>>(bo1, bo2, Wp1, bp1, Wp2, bp2, out);
}

// round 5
// speedup vs baseline: 1.5974x; 1.0181x over previous
#include <cuda_runtime.h>

#define N 1024
#define H 96
#define E 16384

// ---------------- scratch (device globals; no allocation allowed) ----------
__device__ float g_bufA[N*H];
__device__ float g_bufB[N*H];
__device__ float g_m[N*H];
__device__ float g_s[N*H];
__device__ int   g_icnt[N];
__device__ float g_hi[N*H];            // pre-scaled by 0.5
__device__ float g_hjb[N*H];           // pre-scaled by 0.5, includes ba1
__device__ int   g_src[E];
__device__ int   g_tgt[E];
__device__ unsigned short g_list[N*N]; // compacted active-j per row (sorted asc)
__device__ int   g_rcnt[N];
__device__ float g_WihT[96*288];
__device__ float g_WhhT[96*288];
__device__ float g_WaiT[96*96];
__device__ float g_WajT[96*96];
__device__ float g_Wo1T[96*96];
__device__ float g_Wo2T[96*96];

__device__ __forceinline__ float tanha(float v){
    float t; asm("tanh.approx.f32 %0, %1;" : "=f"(t) : "f"(v)); return t;
}
__device__ __forceinline__ float sigt(float v){        // 1 MUFU sigmoid
    return fmaf(0.5f, tanha(0.5f*v), 0.5f);
}
__device__ __forceinline__ float sig_acc(float v){     // accurate (final outputs)
    float e; asm("ex2.approx.f32 %0, %1;" : "=f"(e) : "f"(v * -1.4426950408889634f));
    float r; asm("rcp.approx.f32 %0, %1;" : "=f"(r) : "f"(1.0f + e));
    return r;
}
__device__ __forceinline__ float leaky(float v){
    return (v >= 0.0f) ? v : 0.01f * v;
}

// ---------------- prep: weight transposes + zero histogram ------------------
__global__ void k_prep(const float* __restrict__ Wih, const float* __restrict__ Whh,
                       const float* __restrict__ Wa1,
                       const float* __restrict__ Wo1, const float* __restrict__ Wo2){
    int t = blockIdx.x * blockDim.x + threadIdx.x;
    if (t < N) g_icnt[t] = 0;
    if (t < 288*96){
        int c = t / 96, k = t % 96;
        g_WihT[k*288 + c] = Wih[t];
        g_WhhT[k*288 + c] = Whh[t];
    }
    if (t < 96*192){
        int h = t / 192, k2 = t % 192;
        float v = Wa1[t];
        if (k2 < 96) g_WaiT[k2*96 + h] = v;
        else         g_WajT[(k2-96)*96 + h] = v;
    }
    if (t < 96*96){
        int h = t / 96, k = t % 96;
        g_Wo1T[k*96 + h] = Wo1[t];
        g_Wo2T[k*96 + h] = Wo2[t];
    }
}

// ---------------- decode edge_index (int64 vs int32 storage) + histogram ----
__global__ void k_decode(const int* __restrict__ ei32){
    int e = blockIdx.x * blockDim.x + threadIdx.x;
    if (e >= E) return;
    int odd_or = 0;
    #pragma unroll
    for (int q = 0; q < 16; q++) odd_or |= ei32[2*q + 1];
    int s, t;
    if (odd_or == 0){ s = ei32[2*e];  t = ei32[2*(E + e)]; }   // int64 layout
    else            { s = ei32[e];    t = ei32[E + e];      }  // int32 layout
    if ((unsigned)s >= N) s = -1;
    if ((unsigned)t >= N) t = -1;
    g_src[e] = s;
    g_tgt[e] = t;
    if (t >= 0) atomicAdd(&g_icnt[t], 1);
}

// ---------------- compact adjacency rows (preloaded, ballot scan) -----------
__global__ void k_rows(const int* __restrict__ adj){
    int warp = threadIdx.x >> 5, lane = threadIdx.x & 31;
    int row = blockIdx.x * 8 + warp;
    const int* arow = adj + row * N;
    int av[32];
    #pragma unroll
    for (int w = 0; w < 32; w++) av[w] = arow[w*32 + lane];   // batched MLP
    int base = 0;
    #pragma unroll
    for (int w = 0; w < 32; w++){
        unsigned m = __ballot_sync(0xffffffffu, av[w] == 1);
        if (av[w] == 1){
            int pos = base + __popc(m & ((1u << lane) - 1u));
            g_list[row*N + pos] = (unsigned short)(w*32 + lane);
        }
        base += __popc(m);
    }
    if (lane == 0) g_rcnt[row] = base;
}

// ---------------- init: x = leaky(x[:, :9] @ W_init.T + b_init) -------------
__global__ void k_init(const float* __restrict__ xin, const float* __restrict__ Wi,
                       const float* __restrict__ bi){
    int r = threadIdx.x / 96, h = threadIdx.x % 96;
    int n = blockIdx.x * 4 + r;
    __shared__ float xr[4][10];
    if (threadIdx.x < 40){
        int rr = threadIdx.x / 10, c = threadIdx.x % 10;
        xr[rr][c] = xin[(blockIdx.x*4 + rr)*10 + c];
    }
    __syncthreads();
    float a = bi[h];
    #pragma unroll
    for (int k = 0; k < 9; k++) a = fmaf(xr[r][k], Wi[h*9 + k], a);
    g_bufA[n*H + h] = leaky(a);
}

// ---------------- m = x @ W_ggc ; zero s (only used before unroll 0) --------
__global__ void k_mm(int src, const float* __restrict__ Wg){
    const float* x = src ? g_bufB : g_bufA;
    int tid = threadIdx.x;
    int r = tid / 96, h = tid % 96;
    int base = blockIdx.x * 384;
    __shared__ float xr[4][96];
    xr[r][h] = x[base + tid];
    __syncthreads();
    float a0 = 0.f, a1 = 0.f;
    #pragma unroll 8
    for (int k = 0; k < 96; k += 2){
        a0 = fmaf(xr[r][k],   Wg[k*96 + h],     a0);
        a1 = fmaf(xr[r][k+1], Wg[(k+1)*96 + h], a1);
    }
    g_m[base + tid] = a0 + a1;
    g_s[base + tid] = 0.f;
}

// ---------------- segment sum over edges (thread per (edge,h)) --------------
__global__ void k_scatter(){
    int g = blockIdx.x * 256 + threadIdx.x;   // g < E*96
    int e = g / 96, h = g - e*96;
    int s = g_src[e];
    int t = g_tgt[e];
    if (s >= 0 && t >= 0)
        atomicAdd(&g_s[t*96 + h], g_m[s*96 + h]);
}

// ---------------- GRU update + 0.5-scaled attention features ----------------
__global__ __launch_bounds__(384) void k_gru(int src,
                      const float* __restrict__ bih, const float* __restrict__ bhh,
                      const float* __restrict__ ba1){
    float* x = src ? g_bufB : g_bufA;
    int tid = threadIdx.x;
    int r = tid / 96, h = tid - r*96;
    int n = blockIdx.x * 4 + r;
    int base = blockIdx.x * 384;
    __shared__ float ag[4][96], xr[4][96], xn[4][96];
    {
        float c = (float)g_icnt[n];
        float inv;
        asm("rcp.approx.f32 %0, %1;" : "=f"(inv) : "f"(fmaxf(c, 1.0f)));
        ag[r][h] = g_s[base + tid] * inv;
        xr[r][h] = x[base + tid];
    }
    __syncthreads();
    float gir = bih[h], giz = bih[h+96], gin = bih[h+192];
    float ghr = bhh[h], ghz = bhh[h+96], ghn = bhh[h+192];
    #pragma unroll 4
    for (int k = 0; k < 96; k++){
        float a = ag[r][k], xv = xr[r][k];
        gir = fmaf(a,  g_WihT[k*288 + h],       gir);
        giz = fmaf(a,  g_WihT[k*288 + h + 96],  giz);
        gin = fmaf(a,  g_WihT[k*288 + h + 192], gin);
        ghr = fmaf(xv, g_WhhT[k*288 + h],       ghr);
        ghz = fmaf(xv, g_WhhT[k*288 + h + 96],  ghz);
        ghn = fmaf(xv, g_WhhT[k*288 + h + 192], ghn);
    }
    float rr = sigt(gir + ghr);
    float zz = sigt(giz + ghz);
    float nn = tanha(gin + rr * ghn);
    float xv = (1.0f - zz) * nn + zz * xr[r][h];
    xn[r][h] = xv;
    x[base + tid] = xv;
    __syncthreads();
    float hiv = 0.f, hjv = ba1[h];
    #pragma unroll 4
    for (int k = 0; k < 96; k++){
        float xk = xn[r][k];
        hiv = fmaf(xk, g_WaiT[k*96 + h], hiv);
        hjv = fmaf(xk, g_WajT[k*96 + h], hjv);
    }
    g_hi[n*96 + h]  = 0.5f * hiv;      // fold the /2 of sigt into the features
    g_hjb[n*96 + h] = 0.5f * hjv;
}

// ---------------- fused attention: warp-per-pair, k across lanes ------------
// c_ij = sig( sum_k sig(hi+hj)*Wa2[k] + ba2 );  x_out[i,:] = sum_j c_ij x[j,:]
// Also computes next-unroll m = x_out @ W_ggc and zeroes g_s.
__global__ __launch_bounds__(384) void k_att(int src,
                      const float* __restrict__ Wa2, const float* __restrict__ ba2,
                      const float* __restrict__ Wg){
    const float* x = src ? g_bufB : g_bufA;
    float* xout    = src ? g_bufA : g_bufB;
    int i0 = blockIdx.x * 4;
    int tid = threadIdx.x, wid = tid >> 5, lane = tid & 31;
    int wrow = wid / 3, wsub = wid - wrow*3;     // 3 warps per row
    int irow = i0 + wrow;

    // per-lane constants: half-weights and hi chunks
    float w0 = 0.5f*Wa2[lane], w1 = 0.5f*Wa2[lane+32], w2 = 0.5f*Wa2[lane+64];
    float hi0 = g_hi[irow*96 + lane];
    float hi1 = g_hi[irow*96 + lane + 32];
    float hi2 = g_hi[irow*96 + lane + 64];
    // bias' = ba2 + 0.5*sum(Wa2)  (since sig = 0.5 tanh + 0.5)
    float ws = w0 + w1 + w2;
    #pragma unroll
    for (int o = 16; o; o >>= 1) ws += __shfl_xor_sync(0xffffffffu, ws, o);
    float bbp = ba2[0] + ws;

    int cnt = g_rcnt[irow];
    const unsigned short* lst = g_list + irow*N;
    float acc0 = 0.f, acc1 = 0.f, acc2 = 0.f;

    for (int p = wsub*2; p < cnt; p += 6){        // 2-pair ILP per warp
        int j0 = lst[p];
        bool v1 = (p + 1) < cnt;
        int j1 = v1 ? lst[p+1] : j0;
        const float* h0p = g_hjb + j0*96;
        const float* h1p = g_hjb + j1*96;
        float s0 =      w0 * tanha(hi0 + h0p[lane]);
        s0 = fmaf(w1, tanha(hi1 + h0p[lane+32]), s0);
        s0 = fmaf(w2, tanha(hi2 + h0p[lane+64]), s0);
        float s1 =      w0 * tanha(hi0 + h1p[lane]);
        s1 = fmaf(w1, tanha(hi1 + h1p[lane+32]), s1);
        s1 = fmaf(w2, tanha(hi2 + h1p[lane+64]), s1);
        #pragma unroll
        for (int o = 16; o; o >>= 1){
            s0 += __shfl_xor_sync(0xffffffffu, s0, o);
            s1 += __shfl_xor_sync(0xffffffffu, s1, o);
        }
        float c0 = fmaf(0.5f, tanha(0.5f*(s0 + bbp)), 0.5f);
        float c1 = fmaf(0.5f, tanha(0.5f*(s1 + bbp)), 0.5f);
        const float* x0p = x + j0*96;
        acc0 = fmaf(c0, x0p[lane],    acc0);
        acc1 = fmaf(c0, x0p[lane+32], acc1);
        acc2 = fmaf(c0, x0p[lane+64], acc2);
        if (v1){
            const float* x1p = x + j1*96;
            acc0 = fmaf(c1, x1p[lane],    acc0);
            acc1 = fmaf(c1, x1p[lane+32], acc1);
            acc2 = fmaf(c1, x1p[lane+64], acc2);
        }
    }

    // merge the 3 warps of each row
    __shared__ float accs[12][96];
    accs[wid][lane]    = acc0;
    accs[wid][lane+32] = acc1;
    accs[wid][lane+64] = acc2;
    __syncthreads();
    int rB = tid / 96, hB = tid - rB*96;
    float xv = accs[rB*3][hB] + accs[rB*3+1][hB] + accs[rB*3+2][hB];
    xout[(i0 + rB)*96 + hB] = xv;

    // fused: m = x_new @ W_ggc for the next unroll; zero s
    __shared__ float xr[4][96];
    xr[rB][hB] = xv;
    __syncthreads();
    float a0 = 0.f, a1 = 0.f;
    #pragma unroll 8
    for (int k = 0; k < 96; k += 2){
        a0 = fmaf(xr[rB][k],   Wg[k*96 + hB],     a0);
        a1 = fmaf(xr[rB][k+1], Wg[(k+1)*96 + hB], a1);
    }
    g_m[(i0 + rB)*96 + hB] = a0 + a1;
    g_s[(i0 + rB)*96 + hB] = 0.f;
}

// ---------------- output head -----------------------------------------------
__global__ void k_out(const float* __restrict__ bo1, const float* __restrict__ bo2,
                      const float* __restrict__ Wp1, const float* __restrict__ bp1,
                      const float* __restrict__ Wp2, const float* __restrict__ bp2,
                      float* __restrict__ out){
    const float* x = g_bufA;   // after 2 unrolls data sits in bufA
    int n = blockIdx.x, h = threadIdx.x;
    int w = h >> 5, lane = h & 31;
    __shared__ float x0[96], x1[96], sw1[3], sw2[3];
    x0[h] = x[n*96 + h];
    __syncthreads();
    float a = bo1[h];
    #pragma unroll 4
    for (int k = 0; k < 96; k++) a = fmaf(x0[k], g_Wo1T[k*96 + h], a);
    x1[h] = leaky(a);
    __syncthreads();
    float b = bo2[h];
    #pragma unroll 4
    for (int k = 0; k < 96; k++) b = fmaf(x1[k], g_Wo2T[k*96 + h], b);
    float v = leaky(b);
    float r1 = v * Wp1[h];
    float r2 = v * Wp2[h];
    #pragma unroll
    for (int o = 16; o; o >>= 1){
        r1 += __shfl_xor_sync(0xffffffffu, r1, o);
        r2 += __shfl_xor_sync(0xffffffffu, r2, o);
    }
    if (lane == 0){ sw1[w] = r1; sw2[w] = r2; }
    __syncthreads();
    if (h == 0){
        out[n]     = sig_acc(sw1[0] + sw1[1] + sw1[2] + bp1[0]);
        out[N + n] = sig_acc(sw2[0] + sw2[1] + sw2[2] + bp2[0]);
    }
}

// ---------------- launch -----------------------------------------------------
extern "C" void kernel_launch(void* const* d_in, const int* in_sizes, int n_in,
                              void* d_out, int out_size){
    const float* x_in  = (const float*)d_in[0];
    const int*   ei32  = (const int*)d_in[1];
    const int*   adj   = (const int*)d_in[2];
    const float* W_init= (const float*)d_in[3];
    const float* b_init= (const float*)d_in[4];
    const float* W_ggc = (const float*)d_in[5];
    const float* W_ih  = (const float*)d_in[6];
    const float* W_hh  = (const float*)d_in[7];
    const float* b_ih  = (const float*)d_in[8];
    const float* b_hh  = (const float*)d_in[9];
    const float* Wa1   = (const float*)d_in[10];
    const float* ba1   = (const float*)d_in[11];
    const float* Wa2   = (const float*)d_in[12];
    const float* ba2   = (const float*)d_in[13];
    const float* Wo1   = (const float*)d_in[14];
    const float* bo1   = (const float*)d_in[15];
    const float* Wo2   = (const float*)d_in[16];
    const float* bo2   = (const float*)d_in[17];
    const float* Wp1   = (const float*)d_in[18];
    const float* bp1   = (const float*)d_in[19];
    const float* Wp2   = (const float*)d_in[20];
    const float* bp2   = (const float*)d_in[21];
    float* out = (float*)d_out;

    k_prep<<<(288*96 + 255)/256, 256>>>(W_ih, W_hh, Wa1, Wo1, Wo2);
    k_decode<<<E/256, 256>>>(ei32);
    k_rows<<<N/8, 256>>>(adj);
    k_init<<<N/4, 384>>>(x_in, W_init, b_init);
    k_mm<<<N/4, 384>>>(0, W_ggc);          // m for unroll 0; k_att fuses the rest
    for (int u = 0; u < 2; u++){
        k_scatter<<<(E*96)/256, 256>>>();
        k_gru<<<N/4, 384>>>(u, b_ih, b_hh, ba1);
        k_att<<<N/4, 384>>>(u, Wa2, ba2, W_ggc);
    }
    k_out<<<N, 96>>>(bo1, bo2, Wp1, bp1, Wp2, bp2, out);
}

// round 6
// speedup vs baseline: 1.6300x; 1.0204x over previous
#include <cuda_runtime.h>

#define N 1024
#define H 96
#define E 16384

// ---------------- scratch (device globals; no allocation allowed) ----------
__device__ float g_bufA[N*H];
__device__ float g_bufB[N*H];
__device__ float g_m[N*H];
__device__ int   g_hist[N];            // zero at load; re-zeroed by k_att(u=1)
__device__ int   g_off[N+1];
__device__ int   g_cur[N];
__device__ float g_hi[N*H];            // pre-scaled by 0.5
__device__ float g_hjb[N*H];           // pre-scaled by 0.5, includes ba1
__device__ int   g_src[E];
__device__ int   g_tgt[E];
__device__ int   g_esrc[E];            // CSR payload (src per target-sorted slot)
__device__ unsigned short g_list[N*N]; // compacted active-j per row (sorted asc)
__device__ int   g_rcnt[N];
__device__ float g_WihT[96*288];
__device__ float g_WhhT[96*288];
__device__ float g_WaiT[96*96];
__device__ float g_WajT[96*96];
__device__ float g_Wo1T[96*96];
__device__ float g_Wo2T[96*96];

__device__ __forceinline__ float tanha(float v){
    float t; asm("tanh.approx.f32 %0, %1;" : "=f"(t) : "f"(v)); return t;
}
__device__ __forceinline__ float sigt(float v){        // 1-MUFU sigmoid
    return fmaf(0.5f, tanha(0.5f*v), 0.5f);
}
__device__ __forceinline__ float sig_acc(float v){     // accurate (final outputs)
    float e; asm("ex2.approx.f32 %0, %1;" : "=f"(e) : "f"(v * -1.4426950408889634f));
    float r; asm("rcp.approx.f32 %0, %1;" : "=f"(r) : "f"(1.0f + e));
    return r;
}
__device__ __forceinline__ float leaky(float v){
    return (v >= 0.0f) ? v : 0.01f * v;
}

// ---- 1. prep: weight transposes + edge decode + target histogram ----------
__global__ void k_pre(const float* __restrict__ Wih, const float* __restrict__ Whh,
                      const float* __restrict__ Wa1,
                      const float* __restrict__ Wo1, const float* __restrict__ Wo2,
                      const int* __restrict__ ei32){
    int t = blockIdx.x * 256 + threadIdx.x;
    if (t < 288*96){
        int c = t / 96, k = t % 96;
        g_WihT[k*288 + c] = Wih[t];
        g_WhhT[k*288 + c] = Whh[t];
    }
    if (t < 96*192){
        int h = t / 192, k2 = t % 192;
        float v = Wa1[t];
        if (k2 < 96) g_WaiT[k2*96 + h] = v;
        else         g_WajT[(k2-96)*96 + h] = v;
    }
    if (t < 96*96){
        int h = t / 96, k = t % 96;
        g_Wo1T[k*96 + h] = Wo1[t];
        g_Wo2T[k*96 + h] = Wo2[t];
    }
    if (t < E){
        int odd_or = 0;
        #pragma unroll
        for (int q = 0; q < 16; q++) odd_or |= ei32[2*q + 1];
        int s, tt;
        if (odd_or == 0){ s = ei32[2*t];  tt = ei32[2*(E + t)]; }  // int64 layout
        else            { s = ei32[t];    tt = ei32[E + t];     }  // int32 layout
        if ((unsigned)s >= N || (unsigned)tt >= N){ s = -1; tt = -1; }
        g_src[t] = s;
        g_tgt[t] = tt;
        if (tt >= 0) atomicAdd(&g_hist[tt], 1);
    }
}

// ---- 2. exclusive scan of histogram -> CSR offsets + cursors ---------------
__global__ void k_scan(){
    __shared__ int sc[1024];
    int t = threadIdx.x;
    int v = g_hist[t];
    sc[t] = v;
    __syncthreads();
    for (int o = 1; o < 1024; o <<= 1){
        int add = (t >= o) ? sc[t - o] : 0;
        __syncthreads();
        sc[t] += add;
        __syncthreads();
    }
    int excl = sc[t] - v;
    g_off[t] = excl;
    g_cur[t] = excl;
    if (t == 1023) g_off[1024] = sc[1023];
}

// ---- 3. CSR fill (blocks 0..63) + init & first m=x@Wg (blocks 64..319) -----
__global__ __launch_bounds__(384) void k_fi(const float* __restrict__ xin,
                      const float* __restrict__ Wi, const float* __restrict__ bi,
                      const float* __restrict__ Wg){
    int b = blockIdx.x;
    if (b < 64){
        if (threadIdx.x < 256){
            int e = b*256 + threadIdx.x;
            int tt = g_tgt[e];
            if (tt >= 0){
                int pos = atomicAdd(&g_cur[tt], 1);
                g_esrc[pos] = g_src[e];
            }
        }
        return;
    }
    int bb = b - 64;
    int r = threadIdx.x / 96, h = threadIdx.x % 96;
    int n = bb*4 + r;
    __shared__ float xr[4][10], xs[4][96];
    if (threadIdx.x < 40){
        int rr = threadIdx.x / 10, c = threadIdx.x % 10;
        xr[rr][c] = xin[(bb*4 + rr)*10 + c];
    }
    __syncthreads();
    float a = bi[h];
    #pragma unroll
    for (int k = 0; k < 9; k++) a = fmaf(xr[r][k], Wi[h*9 + k], a);
    float xv = leaky(a);
    g_bufA[n*96 + h] = xv;
    xs[r][h] = xv;
    __syncthreads();
    float a0 = 0.f, a1 = 0.f;
    #pragma unroll 8
    for (int k = 0; k < 96; k += 2){
        a0 = fmaf(xs[r][k],   Wg[k*96 + h],     a0);
        a1 = fmaf(xs[r][k+1], Wg[(k+1)*96 + h], a1);
    }
    g_m[n*96 + h] = a0 + a1;
}

// ---- 4. GRU: CSR gather-agg + gates + attention features (2 nodes/thread) --
__global__ __launch_bounds__(192) void k_gru(int srcbuf,
                      const float* __restrict__ bih, const float* __restrict__ bhh,
                      const float* __restrict__ ba1){
    float* x = srcbuf ? g_bufB : g_bufA;
    int tid = threadIdx.x;
    int h = tid % 96, half = tid / 96;     // half in {0,1}
    int nb = blockIdx.x * 4;
    __shared__ float ag[4][96], xr[4][96], xn[4][96];
    #pragma unroll
    for (int r = 0; r < 2; r++){
        int rr = half*2 + r;
        int n = nb + rr;
        int o0 = g_off[n], o1 = g_off[n+1];
        float s0 = 0.f, s1 = 0.f;
        int p = o0;
        for (; p + 2 <= o1; p += 2){
            int ja = g_esrc[p], jb = g_esrc[p+1];
            s0 += g_m[ja*96 + h];
            s1 += g_m[jb*96 + h];
        }
        if (p < o1) s0 += g_m[g_esrc[p]*96 + h];
        float inv;
        asm("rcp.approx.f32 %0, %1;" : "=f"(inv) : "f"(fmaxf((float)(o1 - o0), 1.0f)));
        ag[rr][h] = (s0 + s1) * inv;
        xr[rr][h] = x[n*96 + h];
    }
    __syncthreads();
    float gir[2], giz[2], gin[2], ghr[2], ghz[2], ghn[2];
    #pragma unroll
    for (int r = 0; r < 2; r++){
        gir[r] = bih[h]; giz[r] = bih[h+96]; gin[r] = bih[h+192];
        ghr[r] = bhh[h]; ghz[r] = bhh[h+96]; ghn[r] = bhh[h+192];
    }
    #pragma unroll 4
    for (int k = 0; k < 96; k++){
        float wir = g_WihT[k*288 + h], wiz = g_WihT[k*288 + h + 96], win = g_WihT[k*288 + h + 192];
        float whr = g_WhhT[k*288 + h], whz = g_WhhT[k*288 + h + 96], whn = g_WhhT[k*288 + h + 192];
        #pragma unroll
        for (int r = 0; r < 2; r++){
            float a = ag[half*2 + r][k], xv = xr[half*2 + r][k];
            gir[r] = fmaf(a,  wir, gir[r]); giz[r] = fmaf(a,  wiz, giz[r]); gin[r] = fmaf(a,  win, gin[r]);
            ghr[r] = fmaf(xv, whr, ghr[r]); ghz[r] = fmaf(xv, whz, ghz[r]); ghn[r] = fmaf(xv, whn, ghn[r]);
        }
    }
    #pragma unroll
    for (int r = 0; r < 2; r++){
        int rr = half*2 + r;
        float rg = sigt(gir[r] + ghr[r]);
        float zg = sigt(giz[r] + ghz[r]);
        float ng = tanha(gin[r] + rg * ghn[r]);
        float xv = (1.0f - zg) * ng + zg * xr[rr][h];
        xn[rr][h] = xv;
        x[(nb + rr)*96 + h] = xv;
    }
    __syncthreads();
    float hiv[2], hjv[2];
    #pragma unroll
    for (int r = 0; r < 2; r++){ hiv[r] = 0.f; hjv[r] = ba1[h]; }
    #pragma unroll 4
    for (int k = 0; k < 96; k++){
        float wi = g_WaiT[k*96 + h], wj = g_WajT[k*96 + h];
        #pragma unroll
        for (int r = 0; r < 2; r++){
            float xk = xn[half*2 + r][k];
            hiv[r] = fmaf(xk, wi, hiv[r]);
            hjv[r] = fmaf(xk, wj, hjv[r]);
        }
    }
    #pragma unroll
    for (int r = 0; r < 2; r++){
        int n = nb + half*2 + r;
        g_hi[n*96 + h]  = 0.5f * hiv[r];
        g_hjb[n*96 + h] = 0.5f * hjv[r];
    }
}

// ---- 5. compact adjacency rows (preloaded, ballot scan) --------------------
__global__ void k_rows(const int* __restrict__ adj){
    int warp = threadIdx.x >> 5, lane = threadIdx.x & 31;
    int row = blockIdx.x * 8 + warp;
    const int* arow = adj + row * N;
    int av[32];
    #pragma unroll
    for (int w = 0; w < 32; w++) av[w] = arow[w*32 + lane];
    int base = 0;
    #pragma unroll
    for (int w = 0; w < 32; w++){
        unsigned m = __ballot_sync(0xffffffffu, av[w] == 1);
        if (av[w] == 1){
            int pos = base + __popc(m & ((1u << lane) - 1u));
            g_list[row*N + pos] = (unsigned short)(w*32 + lane);
        }
        base += __popc(m);
    }
    if (lane == 0) g_rcnt[row] = base;
}

// ---- 6/8. attention (warp-per-pair) + [mode0: xout,next-m | mode1: head] ---
__global__ __launch_bounds__(384) void k_att(int mode,
                      const float* __restrict__ Wa2, const float* __restrict__ ba2,
                      const float* __restrict__ Wg,
                      const float* __restrict__ bo1, const float* __restrict__ bo2,
                      const float* __restrict__ Wp1, const float* __restrict__ bp1,
                      const float* __restrict__ Wp2, const float* __restrict__ bp2,
                      float* __restrict__ out){
    const float* x = mode ? g_bufB : g_bufA;   // u=0 reads bufA, u=1 reads bufB
    float* xout    = g_bufB;                   // only written in mode 0
    int i0 = blockIdx.x * 4;
    int tid = threadIdx.x, wid = tid >> 5, lane = tid & 31;
    int wrow = wid / 3, wsub = wid - wrow*3;
    int irow = i0 + wrow;

    float w0 = 0.5f*Wa2[lane], w1 = 0.5f*Wa2[lane+32], w2 = 0.5f*Wa2[lane+64];
    float hi0 = g_hi[irow*96 + lane];
    float hi1 = g_hi[irow*96 + lane + 32];
    float hi2 = g_hi[irow*96 + lane + 64];
    float ws = w0 + w1 + w2;
    #pragma unroll
    for (int o = 16; o; o >>= 1) ws += __shfl_xor_sync(0xffffffffu, ws, o);
    float bbp = ba2[0] + ws;

    int cnt = g_rcnt[irow];
    const unsigned short* lst = g_list + irow*N;
    float acc0 = 0.f, acc1 = 0.f, acc2 = 0.f;

    for (int p = wsub*2; p < cnt; p += 6){
        int j0 = lst[p];
        bool v1 = (p + 1) < cnt;
        int j1 = v1 ? lst[p+1] : j0;
        const float* h0p = g_hjb + j0*96;
        const float* h1p = g_hjb + j1*96;
        float s0 =      w0 * tanha(hi0 + h0p[lane]);
        s0 = fmaf(w1, tanha(hi1 + h0p[lane+32]), s0);
        s0 = fmaf(w2, tanha(hi2 + h0p[lane+64]), s0);
        float s1 =      w0 * tanha(hi0 + h1p[lane]);
        s1 = fmaf(w1, tanha(hi1 + h1p[lane+32]), s1);
        s1 = fmaf(w2, tanha(hi2 + h1p[lane+64]), s1);
        #pragma unroll
        for (int o = 16; o; o >>= 1){
            s0 += __shfl_xor_sync(0xffffffffu, s0, o);
            s1 += __shfl_xor_sync(0xffffffffu, s1, o);
        }
        float c0 = fmaf(0.5f, tanha(0.5f*(s0 + bbp)), 0.5f);
        float c1 = fmaf(0.5f, tanha(0.5f*(s1 + bbp)), 0.5f);
        const float* x0p = x + j0*96;
        acc0 = fmaf(c0, x0p[lane],    acc0);
        acc1 = fmaf(c0, x0p[lane+32], acc1);
        acc2 = fmaf(c0, x0p[lane+64], acc2);
        if (v1){
            const float* x1p = x + j1*96;
            acc0 = fmaf(c1, x1p[lane],    acc0);
            acc1 = fmaf(c1, x1p[lane+32], acc1);
            acc2 = fmaf(c1, x1p[lane+64], acc2);
        }
    }

    __shared__ float accs[12][96];
    accs[wid][lane]    = acc0;
    accs[wid][lane+32] = acc1;
    accs[wid][lane+64] = acc2;
    __syncthreads();
    int rB = tid / 96, hB = tid - rB*96;
    float xv = accs[rB*3][hB] + accs[rB*3+1][hB] + accs[rB*3+2][hB];

    __shared__ float xs[4][96], x1s[4][96];
    xs[rB][hB] = xv;
    __syncthreads();

    if (mode == 0){
        xout[(i0 + rB)*96 + hB] = xv;
        float a0 = 0.f, a1 = 0.f;
        #pragma unroll 8
        for (int k = 0; k < 96; k += 2){
            a0 = fmaf(xs[rB][k],   Wg[k*96 + hB],     a0);
            a1 = fmaf(xs[rB][k+1], Wg[(k+1)*96 + hB], a1);
        }
        g_m[(i0 + rB)*96 + hB] = a0 + a1;
    } else {
        // fused output head (row-local)
        float a = bo1[hB];
        #pragma unroll 4
        for (int k = 0; k < 96; k++) a = fmaf(xs[rB][k], g_Wo1T[k*96 + hB], a);
        x1s[rB][hB] = leaky(a);
        __syncthreads();
        float b = bo2[hB];
        #pragma unroll 4
        for (int k = 0; k < 96; k++) b = fmaf(x1s[rB][k], g_Wo2T[k*96 + hB], b);
        float v = leaky(b);
        float r1 = v * Wp1[hB];
        float r2 = v * Wp2[hB];
        #pragma unroll
        for (int o = 16; o; o >>= 1){
            r1 += __shfl_xor_sync(0xffffffffu, r1, o);
            r2 += __shfl_xor_sync(0xffffffffu, r2, o);
        }
        __shared__ float sw1[12], sw2[12];
        if (lane == 0){ sw1[wid] = r1; sw2[wid] = r2; }
        __syncthreads();
        if (hB == 0){
            int n = i0 + rB;
            out[n]     = sig_acc(sw1[rB*3] + sw1[rB*3+1] + sw1[rB*3+2] + bp1[0]);
            out[N + n] = sig_acc(sw2[rB*3] + sw2[rB*3+1] + sw2[rB*3+2] + bp2[0]);
            g_hist[n] = 0;   // reset for next replay
        }
    }
}

// ---------------- launch -----------------------------------------------------
extern "C" void kernel_launch(void* const* d_in, const int* in_sizes, int n_in,
                              void* d_out, int out_size){
    const float* x_in  = (const float*)d_in[0];
    const int*   ei32  = (const int*)d_in[1];
    const int*   adj   = (const int*)d_in[2];
    const float* W_init= (const float*)d_in[3];
    const float* b_init= (const float*)d_in[4];
    const float* W_ggc = (const float*)d_in[5];
    const float* W_ih  = (const float*)d_in[6];
    const float* W_hh  = (const float*)d_in[7];
    const float* b_ih  = (const float*)d_in[8];
    const float* b_hh  = (const float*)d_in[9];
    const float* Wa1   = (const float*)d_in[10];
    const float* ba1   = (const float*)d_in[11];
    const float* Wa2   = (const float*)d_in[12];
    const float* ba2   = (const float*)d_in[13];
    const float* Wo1   = (const float*)d_in[14];
    const float* bo1   = (const float*)d_in[15];
    const float* Wo2   = (const float*)d_in[16];
    const float* bo2   = (const float*)d_in[17];
    const float* Wp1   = (const float*)d_in[18];
    const float* bp1   = (const float*)d_in[19];
    const float* Wp2   = (const float*)d_in[20];
    const float* bp2   = (const float*)d_in[21];
    float* out = (float*)d_out;

    k_pre<<<108, 256>>>(W_ih, W_hh, Wa1, Wo1, Wo2, ei32);               // 1
    k_scan<<<1, 1024>>>();                                              // 2
    k_fi<<<320, 384>>>(x_in, W_init, b_init, W_ggc);                    // 3
    k_gru<<<N/4, 192>>>(0, b_ih, b_hh, ba1);                            // 4 (profiled)
    k_rows<<<N/8, 256>>>(adj);                                          // 5
    k_att<<<N/4, 384>>>(0, Wa2, ba2, W_ggc, bo1, bo2, Wp1, bp1, Wp2, bp2, out); // 6
    k_gru<<<N/4, 192>>>(1, b_ih, b_hh, ba1);                            // 7
    k_att<<<N/4, 384>>>(1, Wa2, ba2, W_ggc, bo1, bo2, Wp1, bp1, Wp2, bp2, out); // 8
}

// round 7
// speedup vs baseline: 2.6270x; 1.6117x over previous
#include <cuda_runtime.h>

#define N 1024
#define H 96
#define E 16384

// ---------------- scratch (device globals; no allocation allowed) ----------
__device__ float g_bufA[N*H];
__device__ float g_bufB[N*H];
__device__ float g_m[N*H];
__device__ int   g_hist[N];            // zero at load; re-zeroed by k_att(mode1)
__device__ int   g_off[N+1];
__device__ int   g_cur[N];
__device__ float g_hi[N*H];            // pre-scaled by 0.5
__device__ float g_hjb[N*H];           // pre-scaled by 0.5, includes ba1
__device__ int   g_src[E];
__device__ int   g_tgt[E];
__device__ int   g_esrc[E];            // CSR payload (src per target-sorted slot)
__device__ unsigned short g_list[N*N]; // compacted active-j per row (sorted asc)
__device__ int   g_rcnt[N];
__device__ float g_WgT[96*576];        // fused gate weights [k][c]; c<288: Wih, else Whh
__device__ float g_WfT[96*192];        // fused feature weights [k][c]; c<96: Wai, else Waj
__device__ float g_Wo1T[96*96];
__device__ float g_Wo2T[96*96];

__device__ __forceinline__ float tanha(float v){
    float t; asm("tanh.approx.f32 %0, %1;" : "=f"(t) : "f"(v)); return t;
}
__device__ __forceinline__ float sigt(float v){        // 1-MUFU sigmoid
    return fmaf(0.5f, tanha(0.5f*v), 0.5f);
}
__device__ __forceinline__ float sig_acc(float v){     // accurate (final outputs)
    float e; asm("ex2.approx.f32 %0, %1;" : "=f"(e) : "f"(v * -1.4426950408889634f));
    float r; asm("rcp.approx.f32 %0, %1;" : "=f"(r) : "f"(1.0f + e));
    return r;
}
__device__ __forceinline__ float leaky(float v){
    return (v >= 0.0f) ? v : 0.01f * v;
}

// ---- 1. prep: fused weight layouts + head transposes + decode + adj rows ---
__global__ void k_pre(const float* __restrict__ Wih, const float* __restrict__ Whh,
                      const float* __restrict__ Wa1,
                      const float* __restrict__ Wo1, const float* __restrict__ Wo2,
                      const int* __restrict__ ei32, const int* __restrict__ adj){
    if (blockIdx.x >= 216){
        // ---- adjacency row compaction (8 rows per block, ballot scan) ----
        int warp = threadIdx.x >> 5, lane = threadIdx.x & 31;
        int row = (blockIdx.x - 216) * 8 + warp;
        const int* arow = adj + row * N;
        int av[32];
        #pragma unroll
        for (int w = 0; w < 32; w++) av[w] = arow[w*32 + lane];
        int base = 0;
        #pragma unroll
        for (int w = 0; w < 32; w++){
            unsigned m = __ballot_sync(0xffffffffu, av[w] == 1);
            if (av[w] == 1){
                int pos = base + __popc(m & ((1u << lane) - 1u));
                g_list[row*N + pos] = (unsigned short)(w*32 + lane);
            }
            base += __popc(m);
        }
        if (lane == 0) g_rcnt[row] = base;
        return;
    }
    int t = blockIdx.x * 256 + threadIdx.x;   // < 55296
    {   // fused gate weights
        int k = t / 576, c = t - k*576;
        g_WgT[t] = (c < 288) ? Wih[c*96 + k] : Whh[(c-288)*96 + k];
    }
    if (t < 96*192){
        int k = t / 192, c = t - k*192;
        g_WfT[t] = (c < 96) ? Wa1[c*192 + k] : Wa1[(c-96)*192 + 96 + k];
    }
    if (t < 96*96){
        int h = t / 96, k = t - h*96;
        g_Wo1T[k*96 + h] = Wo1[t];
        g_Wo2T[k*96 + h] = Wo2[t];
    }
    if (t < E){
        int odd_or = 0;
        #pragma unroll
        for (int q = 0; q < 16; q++) odd_or |= ei32[2*q + 1];
        int s, tt;
        if (odd_or == 0){ s = ei32[2*t];  tt = ei32[2*(E + t)]; }  // int64 layout
        else            { s = ei32[t];    tt = ei32[E + t];     }  // int32 layout
        if ((unsigned)s >= N || (unsigned)tt >= N){ s = -1; tt = -1; }
        g_src[t] = s;
        g_tgt[t] = tt;
        if (tt >= 0) atomicAdd(&g_hist[tt], 1);
    }
}

// ---- 2. exclusive scan of histogram -> CSR offsets + cursors ---------------
__global__ void k_scan(){
    __shared__ int sc[1024];
    int t = threadIdx.x;
    int v = g_hist[t];
    sc[t] = v;
    __syncthreads();
    for (int o = 1; o < 1024; o <<= 1){
        int add = (t >= o) ? sc[t - o] : 0;
        __syncthreads();
        sc[t] += add;
        __syncthreads();
    }
    int excl = sc[t] - v;
    g_off[t] = excl;
    g_cur[t] = excl;
    if (t == 1023) g_off[1024] = sc[1023];
}

// ---- 3. CSR fill (blocks 0..63) + init & first m=x@Wg (blocks 64..319) -----
__global__ __launch_bounds__(384) void k_fi(const float* __restrict__ xin,
                      const float* __restrict__ Wi, const float* __restrict__ bi,
                      const float* __restrict__ Wg){
    int b = blockIdx.x;
    if (b < 64){
        if (threadIdx.x < 256){
            int e = b*256 + threadIdx.x;
            int tt = g_tgt[e];
            if (tt >= 0){
                int pos = atomicAdd(&g_cur[tt], 1);
                g_esrc[pos] = g_src[e];
            }
        }
        return;
    }
    int bb = b - 64;
    int r = threadIdx.x / 96, h = threadIdx.x % 96;
    int n = bb*4 + r;
    __shared__ float xr[4][10], xs[4][96];
    if (threadIdx.x < 40){
        int rr = threadIdx.x / 10, c = threadIdx.x % 10;
        xr[rr][c] = xin[(bb*4 + rr)*10 + c];
    }
    __syncthreads();
    float a = bi[h];
    #pragma unroll
    for (int k = 0; k < 9; k++) a = fmaf(xr[r][k], Wi[h*9 + k], a);
    float xv = leaky(a);
    g_bufA[n*96 + h] = xv;
    xs[r][h] = xv;
    __syncthreads();
    float a0 = 0.f, a1 = 0.f;
    #pragma unroll 8
    for (int k = 0; k < 96; k += 2){
        a0 = fmaf(xs[r][k],   Wg[k*96 + h],     a0);
        a1 = fmaf(xs[r][k+1], Wg[(k+1)*96 + h], a1);
    }
    g_m[n*96 + h] = a0 + a1;
}

// ---- 4/6. GRU: 2 nodes/block, 576 threads (thread = output column) ---------
__global__ __launch_bounds__(576) void k_gru(int srcbuf,
                      const float* __restrict__ bih, const float* __restrict__ bhh,
                      const float* __restrict__ ba1){
    float* x = srcbuf ? g_bufB : g_bufA;
    int tid = threadIdx.x;
    int nb = blockIdx.x * 2;
    __shared__ float ag[2][96], xr[2][96], xn[2][96];
    __shared__ float dot[2][576];            // gate dots; reused as feature partials

    // --- CSR gather (3-way split per node) + x load ---
    {
        int r = tid / 288, rem = tid - r*288, q = rem / 96, h = rem - q*96;
        int n = nb + r;
        int o0 = g_off[n], o1 = g_off[n+1];
        float s = 0.f;
        for (int p = o0 + q; p < o1; p += 3)
            s += g_m[g_esrc[p]*96 + h];
        dot[r][q*96 + h] = s;                // stash partials
        if (q == 0) xr[r][h] = x[n*96 + h];
    }
    __syncthreads();
    if (tid < 192){
        int r = tid / 96, h = tid - r*96;
        int n = nb + r;
        float deg = (float)(g_off[n+1] - g_off[n]);
        float inv; asm("rcp.approx.f32 %0, %1;" : "=f"(inv) : "f"(fmaxf(deg, 1.0f)));
        ag[r][h] = (dot[r][h] + dot[r][96 + h] + dot[r][192 + h]) * inv;
    }
    __syncthreads();

    // --- 6 gate dots, thread = column c, 2 nodes per thread ---
    {
        int c = tid;
        const float* opA = (c < 288) ? ag[0] : xr[0];
        const float* opB = (c < 288) ? ag[1] : xr[1];
        float bias = (c < 288) ? bih[c] : bhh[c - 288];
        float dA = bias, dB = bias;
        #pragma unroll 8
        for (int k = 0; k < 96; k++){
            float w = g_WgT[k*576 + c];
            dA = fmaf(w, opA[k], dA);
            dB = fmaf(w, opB[k], dB);
        }
        dot[0][c] = dA;
        dot[1][c] = dB;
    }
    __syncthreads();

    // --- gate combination ---
    if (tid < 192){
        int r = tid / 96, h = tid - r*96;
        float rg = sigt(dot[r][h]       + dot[r][288 + h]);
        float zg = sigt(dot[r][96 + h]  + dot[r][384 + h]);
        float ng = tanha(dot[r][192 + h] + rg * dot[r][480 + h]);
        float xv = (1.0f - zg) * ng + zg * xr[r][h];
        xn[r][h] = xv;
        x[(nb + r)*96 + h] = xv;
    }
    __syncthreads();

    // --- attention features: thread = (k-slice s, column c), 2 nodes ---
    {
        int s = tid / 192, c = tid - s*192;
        float fA = 0.f, fB = 0.f;
        int k0 = s * 32;
        #pragma unroll 8
        for (int k = k0; k < k0 + 32; k++){
            float w = g_WfT[k*192 + c];
            fA = fmaf(w, xn[0][k], fA);
            fB = fmaf(w, xn[1][k], fB);
        }
        dot[0][s*192 + c] = fA;
        dot[1][s*192 + c] = fB;
    }
    __syncthreads();
    if (tid < 384){
        int r = tid / 192, c = tid - r*192;
        float val = dot[r][c] + dot[r][192 + c] + dot[r][384 + c];
        int n = nb + r;
        if (c < 96) g_hi[n*96 + c] = 0.5f * val;
        else        g_hjb[n*96 + (c - 96)] = 0.5f * (val + ba1[c - 96]);
    }
}

// ---- 5/7. attention (6 warps/row, 4 rows) + [mode0: xout,m | mode1: head] --
__global__ __launch_bounds__(768) void k_att(int mode,
                      const float* __restrict__ Wa2, const float* __restrict__ ba2,
                      const float* __restrict__ Wg,
                      const float* __restrict__ bo1, const float* __restrict__ bo2,
                      const float* __restrict__ Wp1, const float* __restrict__ bp1,
                      const float* __restrict__ Wp2, const float* __restrict__ bp2,
                      float* __restrict__ out){
    const float* x = mode ? g_bufB : g_bufA;
    float* xout    = g_bufB;
    int i0 = blockIdx.x * 4;
    int tid = threadIdx.x, wid = tid >> 5, lane = tid & 31;
    int wrow = wid / 6, wsub = wid - wrow*6;     // 6 warps per row
    int irow = i0 + wrow;

    float w0 = 0.5f*Wa2[lane], w1 = 0.5f*Wa2[lane+32], w2 = 0.5f*Wa2[lane+64];
    float hi0 = g_hi[irow*96 + lane];
    float hi1 = g_hi[irow*96 + lane + 32];
    float hi2 = g_hi[irow*96 + lane + 64];
    float ws = w0 + w1 + w2;
    #pragma unroll
    for (int o = 16; o; o >>= 1) ws += __shfl_xor_sync(0xffffffffu, ws, o);
    float bbp = ba2[0] + ws;

    int cnt = g_rcnt[irow];
    const unsigned short* lst = g_list + irow*N;
    float acc0 = 0.f, acc1 = 0.f, acc2 = 0.f;

    for (int p = wsub*2; p < cnt; p += 12){
        int j0 = lst[p];
        bool v1 = (p + 1) < cnt;
        int j1 = v1 ? lst[p+1] : j0;
        const float* h0p = g_hjb + j0*96;
        const float* h1p = g_hjb + j1*96;
        float s0 =      w0 * tanha(hi0 + h0p[lane]);
        s0 = fmaf(w1, tanha(hi1 + h0p[lane+32]), s0);
        s0 = fmaf(w2, tanha(hi2 + h0p[lane+64]), s0);
        float s1 =      w0 * tanha(hi0 + h1p[lane]);
        s1 = fmaf(w1, tanha(hi1 + h1p[lane+32]), s1);
        s1 = fmaf(w2, tanha(hi2 + h1p[lane+64]), s1);
        #pragma unroll
        for (int o = 16; o; o >>= 1){
            s0 += __shfl_xor_sync(0xffffffffu, s0, o);
            s1 += __shfl_xor_sync(0xffffffffu, s1, o);
        }
        float c0 = fmaf(0.5f, tanha(0.5f*(s0 + bbp)), 0.5f);
        float c1 = fmaf(0.5f, tanha(0.5f*(s1 + bbp)), 0.5f);
        const float* x0p = x + j0*96;
        acc0 = fmaf(c0, x0p[lane],    acc0);
        acc1 = fmaf(c0, x0p[lane+32], acc1);
        acc2 = fmaf(c0, x0p[lane+64], acc2);
        if (v1){
            const float* x1p = x + j1*96;
            acc0 = fmaf(c1, x1p[lane],    acc0);
            acc1 = fmaf(c1, x1p[lane+32], acc1);
            acc2 = fmaf(c1, x1p[lane+64], acc2);
        }
    }

    __shared__ float accs[24][96];
    accs[wid][lane]    = acc0;
    accs[wid][lane+32] = acc1;
    accs[wid][lane+64] = acc2;
    __syncthreads();

    __shared__ float xs[4][96], x1s[4][96];
    int rB = tid / 96, hB = tid - rB*96;        // valid for tid < 384
    if (tid < 384){
        float xv = accs[rB*6][hB]   + accs[rB*6+1][hB] + accs[rB*6+2][hB]
                 + accs[rB*6+3][hB] + accs[rB*6+4][hB] + accs[rB*6+5][hB];
        xs[rB][hB] = xv;
    }
    __syncthreads();

    if (mode == 0){
        if (tid < 384){
            float xv = xs[rB][hB];
            xout[(i0 + rB)*96 + hB] = xv;
            float a0 = 0.f, a1 = 0.f;
            #pragma unroll 8
            for (int k = 0; k < 96; k += 2){
                a0 = fmaf(xs[rB][k],   Wg[k*96 + hB],     a0);
                a1 = fmaf(xs[rB][k+1], Wg[(k+1)*96 + hB], a1);
            }
            g_m[(i0 + rB)*96 + hB] = a0 + a1;
        }
    } else {
        if (tid < 384){
            float a = bo1[hB];
            #pragma unroll 4
            for (int k = 0; k < 96; k++) a = fmaf(xs[rB][k], g_Wo1T[k*96 + hB], a);
            x1s[rB][hB] = leaky(a);
        }
        __syncthreads();
        __shared__ float sw1[12], sw2[12];
        if (tid < 384){
            float b = bo2[hB];
            #pragma unroll 4
            for (int k = 0; k < 96; k++) b = fmaf(x1s[rB][k], g_Wo2T[k*96 + hB], b);
            float v = leaky(b);
            float r1 = v * Wp1[hB];
            float r2 = v * Wp2[hB];
            #pragma unroll
            for (int o = 16; o; o >>= 1){
                r1 += __shfl_xor_sync(0xffffffffu, r1, o);
                r2 += __shfl_xor_sync(0xffffffffu, r2, o);
            }
            if (lane == 0){ sw1[wid] = r1; sw2[wid] = r2; }
        }
        __syncthreads();
        if (tid < 384 && hB == 0){
            int n = i0 + rB;
            out[n]     = sig_acc(sw1[rB*3] + sw1[rB*3+1] + sw1[rB*3+2] + bp1[0]);
            out[N + n] = sig_acc(sw2[rB*3] + sw2[rB*3+1] + sw2[rB*3+2] + bp2[0]);
            g_hist[n] = 0;   // reset for next replay
        }
    }
}

// ---------------- launch -----------------------------------------------------
extern "C" void kernel_launch(void* const* d_in, const int* in_sizes, int n_in,
                              void* d_out, int out_size){
    const float* x_in  = (const float*)d_in[0];
    const int*   ei32  = (const int*)d_in[1];
    const int*   adj   = (const int*)d_in[2];
    const float* W_init= (const float*)d_in[3];
    const float* b_init= (const float*)d_in[4];
    const float* W_ggc = (const float*)d_in[5];
    const float* W_ih  = (const float*)d_in[6];
    const float* W_hh  = (const float*)d_in[7];
    const float* b_ih  = (const float*)d_in[8];
    const float* b_hh  = (const float*)d_in[9];
    const float* Wa1   = (const float*)d_in[10];
    const float* ba1   = (const float*)d_in[11];
    const float* Wa2   = (const float*)d_in[12];
    const float* ba2   = (const float*)d_in[13];
    const float* Wo1   = (const float*)d_in[14];
    const float* bo1   = (const float*)d_in[15];
    const float* Wo2   = (const float*)d_in[16];
    const float* bo2   = (const float*)d_in[17];
    const float* Wp1   = (const float*)d_in[18];
    const float* bp1   = (const float*)d_in[19];
    const float* Wp2   = (const float*)d_in[20];
    const float* bp2   = (const float*)d_in[21];
    float* out = (float*)d_out;

    k_pre<<<216 + 128, 256>>>(W_ih, W_hh, Wa1, Wo1, Wo2, ei32, adj);    // 1
    k_scan<<<1, 1024>>>();                                              // 2
    k_fi<<<320, 384>>>(x_in, W_init, b_init, W_ggc);                    // 3
    k_gru<<<N/2, 576>>>(0, b_ih, b_hh, ba1);                            // 4 (profiled)
    k_att<<<N/4, 768>>>(0, Wa2, ba2, W_ggc, bo1, bo2, Wp1, bp1, Wp2, bp2, out); // 5
    k_gru<<<N/2, 576>>>(1, b_ih, b_hh, ba1);                            // 6
    k_att<<<N/4, 768>>>(1, Wa2, ba2, W_ggc, bo1, bo2, Wp1, bp1, Wp2, bp2, out); // 7
}

// round 8
// speedup vs baseline: 2.9831x; 1.1355x over previous
#include <cuda_runtime.h>

#define N 1024
#define H 96
#define E 16384

// ---------------- scratch (device globals; no allocation allowed) ----------
__device__ float g_bufA[N*H];
__device__ float g_bufB[N*H];
__device__ float g_m[N*H];
__device__ int   g_hist[N];            // zero at load; re-zeroed by k_att(mode1)
__device__ int   g_off[N+1];
__device__ int   g_cur[N];
__device__ float g_hi[N*H];            // pre-scaled by 0.5
__device__ float g_hjb[N*H];           // pre-scaled by 0.5, includes ba1
__device__ int   g_src[E];
__device__ int   g_tgt[E];
__device__ int   g_esrc[E];            // CSR payload (src per target-sorted slot)
__device__ unsigned short g_list[N*N]; // compacted active-j per row (sorted asc)
__device__ int   g_rcnt[N];
__device__ float g_WgT[96*576];        // fused gate weights [k][c]; c<288: Wih, else Whh
__device__ float g_WfT[96*192];        // fused feature weights [k][c]; c<96: Wai, else Waj
__device__ float g_Wo1T[96*96];
__device__ float g_Wo2T[96*96];

__device__ __forceinline__ float tanha(float v){
    float t; asm("tanh.approx.f32 %0, %1;" : "=f"(t) : "f"(v)); return t;
}
__device__ __forceinline__ float sigt(float v){        // 1-MUFU sigmoid
    return fmaf(0.5f, tanha(0.5f*v), 0.5f);
}
__device__ __forceinline__ float sig_acc(float v){     // accurate (final outputs)
    float e; asm("ex2.approx.f32 %0, %1;" : "=f"(e) : "f"(v * -1.4426950408889634f));
    float r; asm("rcp.approx.f32 %0, %1;" : "=f"(r) : "f"(1.0f + e));
    return r;
}
__device__ __forceinline__ float leaky(float v){
    return (v >= 0.0f) ? v : 0.01f * v;
}

// ---- 1. prep: fused weight layouts + head transposes + decode + adj rows ---
__global__ void k_pre(const float* __restrict__ Wih, const float* __restrict__ Whh,
                      const float* __restrict__ Wa1,
                      const float* __restrict__ Wo1, const float* __restrict__ Wo2,
                      const int* __restrict__ ei32, const int* __restrict__ adj){
    if (blockIdx.x >= 216){
        // ---- adjacency row compaction (8 rows per block, ballot scan) ----
        int warp = threadIdx.x >> 5, lane = threadIdx.x & 31;
        int row = (blockIdx.x - 216) * 8 + warp;
        const int* arow = adj + row * N;
        int av[32];
        #pragma unroll
        for (int w = 0; w < 32; w++) av[w] = arow[w*32 + lane];
        int base = 0;
        #pragma unroll
        for (int w = 0; w < 32; w++){
            unsigned m = __ballot_sync(0xffffffffu, av[w] == 1);
            if (av[w] == 1){
                int pos = base + __popc(m & ((1u << lane) - 1u));
                g_list[row*N + pos] = (unsigned short)(w*32 + lane);
            }
            base += __popc(m);
        }
        if (lane == 0) g_rcnt[row] = base;
        return;
    }
    int t = blockIdx.x * 256 + threadIdx.x;   // < 55296
    {   // fused gate weights
        int k = t / 576, c = t - k*576;
        g_WgT[t] = (c < 288) ? Wih[c*96 + k] : Whh[(c-288)*96 + k];
    }
    if (t < 96*192){
        int k = t / 192, c = t - k*192;
        g_WfT[t] = (c < 96) ? Wa1[c*192 + k] : Wa1[(c-96)*192 + 96 + k];
    }
    if (t < 96*96){
        int h = t / 96, k = t - h*96;
        g_Wo1T[k*96 + h] = Wo1[t];
        g_Wo2T[k*96 + h] = Wo2[t];
    }
    if (t < E){
        int odd_or = 0;
        #pragma unroll
        for (int q = 0; q < 16; q++) odd_or |= ei32[2*q + 1];
        int s, tt;
        if (odd_or == 0){ s = ei32[2*t];  tt = ei32[2*(E + t)]; }  // int64 layout
        else            { s = ei32[t];    tt = ei32[E + t];     }  // int32 layout
        if ((unsigned)s >= N || (unsigned)tt >= N){ s = -1; tt = -1; }
        g_src[t] = s;
        g_tgt[t] = tt;
        if (tt >= 0) atomicAdd(&g_hist[tt], 1);
    }
}

// ---- 2. exclusive scan of histogram -> CSR offsets + cursors ---------------
__global__ void k_scan(){
    __shared__ int sc[1024];
    int t = threadIdx.x;
    int v = g_hist[t];
    sc[t] = v;
    __syncthreads();
    for (int o = 1; o < 1024; o <<= 1){
        int add = (t >= o) ? sc[t - o] : 0;
        __syncthreads();
        sc[t] += add;
        __syncthreads();
    }
    int excl = sc[t] - v;
    g_off[t] = excl;
    g_cur[t] = excl;
    if (t == 1023) g_off[1024] = sc[1023];
}

// ---- 3. CSR fill (blocks 0..63) + init & first m=x@Wg (blocks 64..319) -----
__global__ __launch_bounds__(384) void k_fi(const float* __restrict__ xin,
                      const float* __restrict__ Wi, const float* __restrict__ bi,
                      const float* __restrict__ Wg){
    int b = blockIdx.x;
    if (b < 64){
        if (threadIdx.x < 256){
            int e = b*256 + threadIdx.x;
            int tt = g_tgt[e];
            if (tt >= 0){
                int pos = atomicAdd(&g_cur[tt], 1);
                g_esrc[pos] = g_src[e];
            }
        }
        return;
    }
    int bb = b - 64;
    int r = threadIdx.x / 96, h = threadIdx.x % 96;
    int n = bb*4 + r;
    __shared__ float xr[4][10], xs[4][96];
    if (threadIdx.x < 40){
        int rr = threadIdx.x / 10, c = threadIdx.x % 10;
        xr[rr][c] = xin[(bb*4 + rr)*10 + c];
    }
    __syncthreads();
    float a = bi[h];
    #pragma unroll
    for (int k = 0; k < 9; k++) a = fmaf(xr[r][k], Wi[h*9 + k], a);
    float xv = leaky(a);
    g_bufA[n*96 + h] = xv;
    xs[r][h] = xv;
    __syncthreads();
    float a0 = 0.f, a1 = 0.f;
    #pragma unroll 8
    for (int k = 0; k < 96; k += 2){
        a0 = fmaf(xs[r][k],   Wg[k*96 + h],     a0);
        a1 = fmaf(xs[r][k+1], Wg[(k+1)*96 + h], a1);
    }
    g_m[n*96 + h] = a0 + a1;
}

// ---- 4/6. GRU: 4 nodes/block, 576 threads (thread = output column) ---------
__global__ __launch_bounds__(576) void k_gru(int srcbuf,
                      const float* __restrict__ bih, const float* __restrict__ bhh,
                      const float* __restrict__ ba1){
    float* x = srcbuf ? g_bufB : g_bufA;
    int tid = threadIdx.x;
    int nb = blockIdx.x * 4;
    __shared__ float ag[4][96], xr[4][96], xn[4][96];
    __shared__ float dot[4][576];            // gate dots; reused as feature partials

    // --- CSR gather: one thread per (node, h) slot + x load ---
    if (tid < 384){
        int r = tid / 96, h = tid - r*96;
        int n = nb + r;
        int o0 = g_off[n], o1 = g_off[n+1];
        float s0 = 0.f, s1 = 0.f;
        int p = o0;
        for (; p + 2 <= o1; p += 2){
            s0 += g_m[g_esrc[p]*96 + h];
            s1 += g_m[g_esrc[p+1]*96 + h];
        }
        if (p < o1) s0 += g_m[g_esrc[p]*96 + h];
        float inv;
        asm("rcp.approx.f32 %0, %1;" : "=f"(inv) : "f"(fmaxf((float)(o1 - o0), 1.0f)));
        ag[r][h] = (s0 + s1) * inv;
        xr[r][h] = x[n*96 + h];
    }
    __syncthreads();

    // --- 6 gate dots, thread = column c, 4 nodes per thread ---
    {
        int c = tid;
        bool isI = c < 288;
        float bias = isI ? bih[c] : bhh[c - 288];
        const float (*op)[96] = isI ? ag : xr;
        float d0 = bias, d1 = bias, d2 = bias, d3 = bias;
        #pragma unroll 8
        for (int k = 0; k < 96; k++){
            float w = g_WgT[k*576 + c];
            d0 = fmaf(w, op[0][k], d0);
            d1 = fmaf(w, op[1][k], d1);
            d2 = fmaf(w, op[2][k], d2);
            d3 = fmaf(w, op[3][k], d3);
        }
        dot[0][c] = d0; dot[1][c] = d1; dot[2][c] = d2; dot[3][c] = d3;
    }
    __syncthreads();

    // --- gate combination ---
    if (tid < 384){
        int r = tid / 96, h = tid - r*96;
        float rg = sigt(dot[r][h]        + dot[r][288 + h]);
        float zg = sigt(dot[r][96 + h]   + dot[r][384 + h]);
        float ng = tanha(dot[r][192 + h] + rg * dot[r][480 + h]);
        float xv = (1.0f - zg) * ng + zg * xr[r][h];
        xn[r][h] = xv;
        x[(nb + r)*96 + h] = xv;
    }
    __syncthreads();

    // --- attention features: thread = (k-slice s of 32, column c), 4 nodes ---
    {
        int s = tid / 192, c = tid - s*192;
        float f0 = 0.f, f1 = 0.f, f2 = 0.f, f3 = 0.f;
        int k0 = s * 32;
        #pragma unroll 8
        for (int k = k0; k < k0 + 32; k++){
            float w = g_WfT[k*192 + c];
            f0 = fmaf(w, xn[0][k], f0);
            f1 = fmaf(w, xn[1][k], f1);
            f2 = fmaf(w, xn[2][k], f2);
            f3 = fmaf(w, xn[3][k], f3);
        }
        dot[0][s*192 + c] = f0;
        dot[1][s*192 + c] = f1;
        dot[2][s*192 + c] = f2;
        dot[3][s*192 + c] = f3;
    }
    __syncthreads();
    for (int s = tid; s < 768; s += 576){
        int r = s / 192, c = s - r*192;
        float val = dot[r][c] + dot[r][192 + c] + dot[r][384 + c];
        int n = nb + r;
        if (c < 96) g_hi[n*96 + c] = 0.5f * val;
        else        g_hjb[n*96 + (c - 96)] = 0.5f * (val + ba1[c - 96]);
    }
}

// ---- 5/7. attention (6 warps/row, 4 rows, 4-pair ILP) ----------------------
__global__ __launch_bounds__(768) void k_att(int mode,
                      const float* __restrict__ Wa2, const float* __restrict__ ba2,
                      const float* __restrict__ Wg,
                      const float* __restrict__ bo1, const float* __restrict__ bo2,
                      const float* __restrict__ Wp1, const float* __restrict__ bp1,
                      const float* __restrict__ Wp2, const float* __restrict__ bp2,
                      float* __restrict__ out){
    const float* x = mode ? g_bufB : g_bufA;
    float* xout    = g_bufB;
    int i0 = blockIdx.x * 4;
    int tid = threadIdx.x, wid = tid >> 5, lane = tid & 31;
    int wrow = wid / 6, wsub = wid - wrow*6;     // 6 warps per row
    int irow = i0 + wrow;

    float w0 = 0.5f*Wa2[lane], w1 = 0.5f*Wa2[lane+32], w2 = 0.5f*Wa2[lane+64];
    float hi0 = g_hi[irow*96 + lane];
    float hi1 = g_hi[irow*96 + lane + 32];
    float hi2 = g_hi[irow*96 + lane + 64];
    float ws = w0 + w1 + w2;
    #pragma unroll
    for (int o = 16; o; o >>= 1) ws += __shfl_xor_sync(0xffffffffu, ws, o);
    float bbp = ba2[0] + ws;

    int cnt = g_rcnt[irow];
    const ushort4* lst4 = (const ushort4*)(g_list + irow*N);
    float acc0 = 0.f, acc1 = 0.f, acc2 = 0.f;

    for (int p4 = wsub; p4*4 < cnt; p4 += 6){
        ushort4 js = lst4[p4];                    // one 8B load, 4 indices
        int p = p4 * 4;
        bool v1 = (p + 1) < cnt, v2 = (p + 2) < cnt, v3 = (p + 3) < cnt;
        int j0 = js.x;
        int j1 = v1 ? (int)js.y : j0;
        int j2 = v2 ? (int)js.z : j0;
        int j3 = v3 ? (int)js.w : j0;
        const float* h0p = g_hjb + j0*96;
        const float* h1p = g_hjb + j1*96;
        const float* h2p = g_hjb + j2*96;
        const float* h3p = g_hjb + j3*96;
        float s0 =      w0 * tanha(hi0 + h0p[lane]);
        float s1 =      w0 * tanha(hi0 + h1p[lane]);
        float s2 =      w0 * tanha(hi0 + h2p[lane]);
        float s3 =      w0 * tanha(hi0 + h3p[lane]);
        s0 = fmaf(w1, tanha(hi1 + h0p[lane+32]), s0);
        s1 = fmaf(w1, tanha(hi1 + h1p[lane+32]), s1);
        s2 = fmaf(w1, tanha(hi1 + h2p[lane+32]), s2);
        s3 = fmaf(w1, tanha(hi1 + h3p[lane+32]), s3);
        s0 = fmaf(w2, tanha(hi2 + h0p[lane+64]), s0);
        s1 = fmaf(w2, tanha(hi2 + h1p[lane+64]), s1);
        s2 = fmaf(w2, tanha(hi2 + h2p[lane+64]), s2);
        s3 = fmaf(w2, tanha(hi2 + h3p[lane+64]), s3);
        #pragma unroll
        for (int o = 16; o; o >>= 1){
            s0 += __shfl_xor_sync(0xffffffffu, s0, o);
            s1 += __shfl_xor_sync(0xffffffffu, s1, o);
            s2 += __shfl_xor_sync(0xffffffffu, s2, o);
            s3 += __shfl_xor_sync(0xffffffffu, s3, o);
        }
        float c0 = fmaf(0.5f, tanha(0.5f*(s0 + bbp)), 0.5f);
        float c1 = v1 ? fmaf(0.5f, tanha(0.5f*(s1 + bbp)), 0.5f) : 0.f;
        float c2 = v2 ? fmaf(0.5f, tanha(0.5f*(s2 + bbp)), 0.5f) : 0.f;
        float c3 = v3 ? fmaf(0.5f, tanha(0.5f*(s3 + bbp)), 0.5f) : 0.f;
        const float* x0p = x + j0*96;
        const float* x1p = x + j1*96;
        const float* x2p = x + j2*96;
        const float* x3p = x + j3*96;
        acc0 = fmaf(c0, x0p[lane],    acc0);
        acc1 = fmaf(c0, x0p[lane+32], acc1);
        acc2 = fmaf(c0, x0p[lane+64], acc2);
        acc0 = fmaf(c1, x1p[lane],    acc0);
        acc1 = fmaf(c1, x1p[lane+32], acc1);
        acc2 = fmaf(c1, x1p[lane+64], acc2);
        acc0 = fmaf(c2, x2p[lane],    acc0);
        acc1 = fmaf(c2, x2p[lane+32], acc1);
        acc2 = fmaf(c2, x2p[lane+64], acc2);
        acc0 = fmaf(c3, x3p[lane],    acc0);
        acc1 = fmaf(c3, x3p[lane+32], acc1);
        acc2 = fmaf(c3, x3p[lane+64], acc2);
    }

    __shared__ float accs[24][96];
    accs[wid][lane]    = acc0;
    accs[wid][lane+32] = acc1;
    accs[wid][lane+64] = acc2;
    __syncthreads();

    __shared__ float xs[4][96], x1s[4][96];
    int rB = tid / 96, hB = tid - rB*96;        // valid for tid < 384
    if (tid < 384){
        float xv = accs[rB*6][hB]   + accs[rB*6+1][hB] + accs[rB*6+2][hB]
                 + accs[rB*6+3][hB] + accs[rB*6+4][hB] + accs[rB*6+5][hB];
        xs[rB][hB] = xv;
    }
    __syncthreads();

    if (mode == 0){
        if (tid < 384){
            float xv = xs[rB][hB];
            xout[(i0 + rB)*96 + hB] = xv;
            float a0 = 0.f, a1 = 0.f;
            #pragma unroll 8
            for (int k = 0; k < 96; k += 2){
                a0 = fmaf(xs[rB][k],   Wg[k*96 + hB],     a0);
                a1 = fmaf(xs[rB][k+1], Wg[(k+1)*96 + hB], a1);
            }
            g_m[(i0 + rB)*96 + hB] = a0 + a1;
        }
    } else {
        if (tid < 384){
            float a = bo1[hB];
            #pragma unroll 4
            for (int k = 0; k < 96; k++) a = fmaf(xs[rB][k], g_Wo1T[k*96 + hB], a);
            x1s[rB][hB] = leaky(a);
        }
        __syncthreads();
        __shared__ float sw1[12], sw2[12];
        if (tid < 384){
            float b = bo2[hB];
            #pragma unroll 4
            for (int k = 0; k < 96; k++) b = fmaf(x1s[rB][k], g_Wo2T[k*96 + hB], b);
            float v = leaky(b);
            float r1 = v * Wp1[hB];
            float r2 = v * Wp2[hB];
            #pragma unroll
            for (int o = 16; o; o >>= 1){
                r1 += __shfl_xor_sync(0xffffffffu, r1, o);
                r2 += __shfl_xor_sync(0xffffffffu, r2, o);
            }
            if (lane == 0){ sw1[wid] = r1; sw2[wid] = r2; }
        }
        __syncthreads();
        if (tid < 384 && hB == 0){
            int n = i0 + rB;
            out[n]     = sig_acc(sw1[rB*3] + sw1[rB*3+1] + sw1[rB*3+2] + bp1[0]);
            out[N + n] = sig_acc(sw2[rB*3] + sw2[rB*3+1] + sw2[rB*3+2] + bp2[0]);
            g_hist[n] = 0;   // reset for next replay
        }
    }
}

// ---------------- launch -----------------------------------------------------
extern "C" void kernel_launch(void* const* d_in, const int* in_sizes, int n_in,
                              void* d_out, int out_size){
    const float* x_in  = (const float*)d_in[0];
    const int*   ei32  = (const int*)d_in[1];
    const int*   adj   = (const int*)d_in[2];
    const float* W_init= (const float*)d_in[3];
    const float* b_init= (const float*)d_in[4];
    const float* W_ggc = (const float*)d_in[5];
    const float* W_ih  = (const float*)d_in[6];
    const float* W_hh  = (const float*)d_in[7];
    const float* b_ih  = (const float*)d_in[8];
    const float* b_hh  = (const float*)d_in[9];
    const float* Wa1   = (const float*)d_in[10];
    const float* ba1   = (const float*)d_in[11];
    const float* Wa2   = (const float*)d_in[12];
    const float* ba2   = (const float*)d_in[13];
    const float* Wo1   = (const float*)d_in[14];
    const float* bo1   = (const float*)d_in[15];
    const float* Wo2   = (const float*)d_in[16];
    const float* bo2   = (const float*)d_in[17];
    const float* Wp1   = (const float*)d_in[18];
    const float* bp1   = (const float*)d_in[19];
    const float* Wp2   = (const float*)d_in[20];
    const float* bp2   = (const float*)d_in[21];
    float* out = (float*)d_out;

    k_pre<<<216 + 128, 256>>>(W_ih, W_hh, Wa1, Wo1, Wo2, ei32, adj);    // 1
    k_scan<<<1, 1024>>>();                                              // 2
    k_fi<<<320, 384>>>(x_in, W_init, b_init, W_ggc);                    // 3
    k_gru<<<N/4, 576>>>(0, b_ih, b_hh, ba1);                            // 4 (profiled)
    k_att<<<N/4, 768>>>(0, Wa2, ba2, W_ggc, bo1, bo2, Wp1, bp1, Wp2, bp2, out); // 5
    k_gru<<<N/4, 576>>>(1, b_ih, b_hh, ba1);                            // 6
    k_att<<<N/4, 768>>>(1, Wa2, ba2, W_ggc, bo1, bo2, Wp1, bp1, Wp2, bp2, out); // 7
}